// round 2
// baseline (speedup 1.0000x reference)
#include <cuda_runtime.h>
#include <cstddef>

#define T_STEPS 300
#define TCH 32
#define NTC 10            // ceil(300/32)
#define THETA 10.0f

// ---------------- scratch (ping-pong) ----------------
__device__ float g_bufA[39321600];   // max needed: 8*16*32*32*300
__device__ float g_bufB[39321600];

// REF_KERNEL[1..10]: -20*t*exp(1-t), t=1..10 (fp32-rounded from double)
__constant__ float c_refk[10] = {
    -20.0f,
    -14.715177646857693f,
    -8.1201169941967624f,
    -3.9829654694291156f,
    -1.8315638888734179f,
    -0.80855363989025606f,
    -0.34702530473329019f,
    -0.14590111448872260f,
    -0.060383273022452132f,
    -0.024681960817335913f
};

__device__ __forceinline__ float spike_step(float u, float (&buf)[10]) {
    float um = u + buf[0];
    float e = (um >= THETA) ? 1.0f : 0.0f;
#pragma unroll
    for (int j = 0; j < 9; j++) buf[j] = buf[j + 1] + e * c_refk[j];
    buf[9] = e * c_refk[9];
    return e;   // TS = 1 -> amplitude 1
}

// ---------------- conv (per-timestep 2D conv, T innermost) ----------------
// block: (b, yo, t-chunk). smem holds padded input rows [Ci][K][WT][TCH].
// Each thread accumulates XR=8 adjacent x outputs with a sliding register window.
template <int Ci, int Hi, int Wi, int Co, int Ho, int Wo, int K, int PAD>
__global__ void conv_kernel(const float* __restrict__ in,
                            const float* __restrict__ w,
                            float* __restrict__ out)
{
    constexpr int WT  = Wo + K - 1;
    constexpr int XR  = 8;
    constexpr int NXG = Wo / XR;
    constexpr int NTY = 8;
    extern __shared__ float sm[];

    int bid = blockIdx.x;
    int tc  = bid % NTC;
    int yo  = (bid / NTC) % Ho;
    int b   = bid / (NTC * Ho);
    int t0  = tc * TCH;

    int tid = threadIdx.y * TCH + threadIdx.x;
    constexpr int NTH = TCH * NTY;

    // load padded input tile
    constexpr int TILE = Ci * K * WT * TCH;
    for (int flat = tid; flat < TILE; flat += NTH) {
        int tt = flat % TCH;
        int r  = flat / TCH;
        int xw = r % WT; r /= WT;
        int ky = r % K;
        int ci = r / K;
        int xi = xw - PAD;
        int yi = yo - PAD + ky;
        int t  = t0 + tt;
        float v = 0.0f;
        if (xi >= 0 && xi < Wi && yi >= 0 && yi < Hi && t < T_STEPS)
            v = in[((((size_t)b * Ci + ci) * Hi + yi) * Wi + xi) * T_STEPS + t];
        sm[flat] = v;
    }
    __syncthreads();

    int tx = threadIdx.x;
    int t  = t0 + tx;

    for (int item = threadIdx.y; item < Co * NXG; item += NTY) {
        int co  = item / NXG;
        int xo0 = (item % NXG) * XR;
        float acc[XR];
#pragma unroll
        for (int r = 0; r < XR; r++) acc[r] = 0.0f;

        for (int ci = 0; ci < Ci; ci++) {
#pragma unroll
            for (int ky = 0; ky < K; ky++) {
                float v[K + XR - 1];
                const float* sp = &sm[((ci * K + ky) * WT + xo0) * TCH + tx];
#pragma unroll
                for (int j = 0; j < K + XR - 1; j++) v[j] = sp[j * TCH];
                const float* wp = &w[((co * Ci + ci) * K + ky) * K];
#pragma unroll
                for (int kx = 0; kx < K; kx++) {
                    float wv = wp[kx];
#pragma unroll
                    for (int r = 0; r < XR; r++)
                        acc[r] = fmaf(v[kx + r], wv, acc[r]);
                }
            }
        }
        if (t < T_STEPS) {
#pragma unroll
            for (int r = 0; r < XR; r++)
                out[((((size_t)b * Co + co) * Ho + yo) * Wo + xo0 + r) * T_STEPS + t] = acc[r];
        }
    }
}

// ---------------- spike: one thread per neuron, sequential over T ----------------
__global__ void spike_kernel(const float* __restrict__ u, float* __restrict__ s, int nNeurons)
{
    int n = blockIdx.x * blockDim.x + threadIdx.x;
    if (n >= nNeurons) return;
    const float4* up = (const float4*)(u + (size_t)n * T_STEPS);
    float4*       sp = (float4*)(s + (size_t)n * T_STEPS);
    float buf[10];
#pragma unroll
    for (int j = 0; j < 10; j++) buf[j] = 0.0f;
    for (int q = 0; q < T_STEPS / 4; q++) {
        float4 uv = up[q];
        float4 ev;
        ev.x = spike_step(uv.x, buf);
        ev.y = spike_step(uv.y, buf);
        ev.z = spike_step(uv.z, buf);
        ev.w = spike_step(uv.w, buf);
        sp[q] = ev;
    }
}

// ---------------- fused 2x2 sum-pool (x 1.1*theta) + spike ----------------
// sin: [8, C, 2Ho, 2Wo, T]  ->  sout: [8, C, Ho, Wo, T]
__global__ void poolspike_kernel(const float* __restrict__ sin, float* __restrict__ sout,
                                 int C, int Ho, int Wo)
{
    int n = blockIdx.x * blockDim.x + threadIdx.x;
    int total = 8 * C * Ho * Wo;
    if (n >= total) return;
    int x  = n % Wo;
    int y  = (n / Wo) % Ho;
    int cb = n / (Wo * Ho);       // b*C + c

    size_t rowT = (size_t)(2 * Wo) * T_STEPS;
    size_t base = (((size_t)cb * (2 * Ho) + 2 * y) * (2 * Wo) + 2 * x) * T_STEPS;
    const float4* p00 = (const float4*)(sin + base);
    const float4* p01 = (const float4*)(sin + base + T_STEPS);
    const float4* p10 = (const float4*)(sin + base + rowT);
    const float4* p11 = (const float4*)(sin + base + rowT + T_STEPS);
    float4* sp = (float4*)(sout + (size_t)n * T_STEPS);

    float buf[10];
#pragma unroll
    for (int j = 0; j < 10; j++) buf[j] = 0.0f;

    for (int q = 0; q < T_STEPS / 4; q++) {
        float4 a = p00[q], b4 = p01[q], c4 = p10[q], d4 = p11[q];
        float4 ev;
        ev.x = spike_step(11.0f * (a.x + b4.x + c4.x + d4.x), buf);
        ev.y = spike_step(11.0f * (a.y + b4.y + c4.y + d4.y), buf);
        ev.z = spike_step(11.0f * (a.z + b4.z + c4.z + d4.z), buf);
        ev.w = spike_step(11.0f * (a.w + b4.w + c4.w + d4.w), buf);
        sp[q] = ev;
    }
}

// ---------------- FC (full-spatial contraction) + final spike ----------------
// s5: [8, 4096, T], wfc: [10, 4096], out: [8, 10, T]
__global__ void fc_spike_kernel(const float* __restrict__ s5, const float* __restrict__ wfc,
                                float* __restrict__ out)
{
    int b = blockIdx.x / 10;
    int o = blockIdx.x % 10;
    __shared__ float u_sm[304];
    __shared__ float psum[8][33];
    int tx = threadIdx.x;   // 32
    int ty = threadIdx.y;   // 8

    const float* sb = s5 + (size_t)b * 4096 * T_STEPS;
    const float* wo = wfc + o * 4096;

    for (int t0 = 0; t0 < T_STEPS; t0 += 32) {
        int t = t0 + tx;
        float acc = 0.0f;
        if (t < T_STEPS) {
            int c0 = ty * 512;
            for (int c = c0; c < c0 + 512; c++)
                acc = fmaf(sb[(size_t)c * T_STEPS + t], wo[c], acc);
        }
        psum[ty][tx] = acc;
        __syncthreads();
        if (ty == 0 && t < T_STEPS) {
            float v = psum[0][tx];
#pragma unroll
            for (int j = 1; j < 8; j++) v += psum[j][tx];
            u_sm[t] = v;
        }
        __syncthreads();
    }

    if (tx == 0 && ty == 0) {
        float buf[10];
#pragma unroll
        for (int j = 0; j < 10; j++) buf[j] = 0.0f;
        float* op = out + (size_t)(b * 10 + o) * T_STEPS;
        for (int t = 0; t < T_STEPS; t++)
            op[t] = spike_step(u_sm[t], buf);
    }
}

// ---------------- launcher ----------------
extern "C" void kernel_launch(void* const* d_in, const int* in_sizes, int n_in,
                              void* d_out, int out_size)
{
    const float* x   = (const float*)d_in[0];   // [8,2,34,34,300]
    const float* w1  = (const float*)d_in[1];   // [16,2,5,5]
    const float* w2  = (const float*)d_in[2];   // [32,16,3,3]
    const float* w3  = (const float*)d_in[3];   // [64,32,3,3]
    const float* wfc = (const float*)d_in[4];   // [10,64,8,8]
    float* out = (float*)d_out;                 // [8,10,1,1,300]

    float *A = nullptr, *B = nullptr;
    cudaGetSymbolAddress((void**)&A, g_bufA);
    cudaGetSymbolAddress((void**)&B, g_bufB);

    cudaFuncSetAttribute(conv_kernel<16,16,16,32,16,16,3,1>,
                         cudaFuncAttributeMaxDynamicSharedMemorySize, 110592);
    cudaFuncSetAttribute(conv_kernel<32,8,8,64,8,8,3,1>,
                         cudaFuncAttributeMaxDynamicSharedMemorySize, 122880);

    // L1: conv 2->16 5x5 pad1 : x -> A (u1)  [8,16,32,32,300]
    conv_kernel<2,34,34,16,32,32,5,1><<<8 * 32 * NTC, dim3(TCH, 8), 46080>>>(x, w1, A);
    // spike1: A -> B (s1)
    spike_kernel<<<131072 / 256, 256>>>(A, B, 131072);
    // pool+spike2: B -> A (s2) [8,16,16,16,300]
    poolspike_kernel<<<32768 / 256, 256>>>(B, A, 16, 16, 16);
    // L2: conv 16->32 3x3 pad1 : A -> B (u3) [8,32,16,16,300]
    conv_kernel<16,16,16,32,16,16,3,1><<<8 * 16 * NTC, dim3(TCH, 8), 110592>>>(A, w2, B);
    // spike3: B -> A (s3)
    spike_kernel<<<65536 / 256, 256>>>(B, A, 65536);
    // pool+spike4: A -> B (s4) [8,32,8,8,300]
    poolspike_kernel<<<16384 / 256, 256>>>(A, B, 32, 8, 8);
    // L3: conv 32->64 3x3 pad1 : B -> A (u5) [8,64,8,8,300]
    conv_kernel<32,8,8,64,8,8,3,1><<<8 * 8 * NTC, dim3(TCH, 8), 122880>>>(B, w3, A);
    // spike5: A -> B (s5)
    spike_kernel<<<32768 / 256, 256>>>(A, B, 32768);
    // FC + final spike: B -> out
    fc_spike_kernel<<<80, dim3(32, 8)>>>(B, wfc, out);
}

// round 5
// speedup vs baseline: 1.1721x; 1.1721x over previous
#include <cuda_runtime.h>
#include <cstddef>

#define T_STEPS 300
#define TCH 32            // timesteps per block chunk
#define TP  16            // float2 pairs per chunk
#define NTC 10            // ceil(300/32)
#define THETA 10.0f

// ---------------- scratch (ping-pong) ----------------
__device__ float g_bufA[39321600];   // max needed: 8*16*32*32*300
__device__ float g_bufB[39321600];

// REF_KERNEL[1..10]: -20*t*exp(1-t), t=1..10 (fp32-rounded from double)
__constant__ float c_refk[10] = {
    -20.0f,
    -14.715177646857693f,
    -8.1201169941967624f,
    -3.9829654694291156f,
    -1.8315638888734179f,
    -0.80855363989025606f,
    -0.34702530473329019f,
    -0.14590111448872260f,
    -0.060383273022452132f,
    -0.024681960817335913f
};

__device__ __forceinline__ float spike_step(float u, float (&buf)[10]) {
    float um = u + buf[0];
    float e = (um >= THETA) ? 1.0f : 0.0f;
#pragma unroll
    for (int j = 0; j < 9; j++) buf[j] = buf[j + 1] + e * c_refk[j];
    buf[9] = e * c_refk[9];
    return e;   // TS = 1 -> amplitude 1
}

// packed 2x fp32 fma (Blackwell FFMA2). Bit-identical to two fmaf's.
__device__ __forceinline__ void ffma2(float2& c, float2 a, float2 b) {
    unsigned long long au = *reinterpret_cast<unsigned long long*>(&a);
    unsigned long long bu = *reinterpret_cast<unsigned long long*>(&b);
    unsigned long long cu = *reinterpret_cast<unsigned long long*>(&c);
    asm("fma.rn.f32x2 %0, %1, %2, %0;" : "+l"(cu) : "l"(au), "l"(bu));
    *reinterpret_cast<unsigned long long*>(&c) = cu;
}

// ---------------- conv (per-timestep 2D conv, T innermost, f32x2 packed) -------
// block: (b, yo, t-chunk of 32 steps = 16 pairs). threads (16,16).
// tx owns timestep pair (t0+2tx, t0+2tx+1); ty owns one (co-group, xo-group) item.
// Each thread computes COB=4 output channels x XR=8 x-positions, so each smem
// window load feeds COB*K FMAs (4x less LDS than one-co-per-thread).
template <int Ci, int Hi, int Wi, int Co, int Ho, int Wo, int K, int PAD>
__global__ void __launch_bounds__(256, 1)
conv_kernel(const float* __restrict__ in, const float* __restrict__ w,
            float* __restrict__ out)
{
    constexpr int WT  = Wo + K - 1;
    constexpr int XR  = 8;
    constexpr int COB = 4;
    constexpr int XG  = Wo / XR;
    constexpr int CG  = Co / COB;
    static_assert(XG * CG == 16, "items must equal blockDim.y");

    extern __shared__ char smraw[];
    float2* sm2 = (float2*)smraw;

    int bid = blockIdx.x;
    int tc  = bid % NTC;
    int yo  = (bid / NTC) % Ho;
    int b   = bid / (NTC * Ho);
    int t0  = tc * TCH;

    int tid = threadIdx.y * 16 + threadIdx.x;

    // ---- load padded input tile as float2 pairs: [Ci][K][WT][TP] ----
    constexpr int TILE2 = Ci * K * WT * TP;
    for (int flat = tid; flat < TILE2; flat += 256) {
        int tt = flat % TP;
        int r  = flat / TP;
        int xw = r % WT; r /= WT;
        int ky = r % K;
        int ci = r / K;
        int xi = xw - PAD;
        int yi = yo - PAD + ky;
        int t  = t0 + 2 * tt;
        float2 v = make_float2(0.0f, 0.0f);
        if (xi >= 0 && xi < Wi && yi >= 0 && yi < Hi && t < T_STEPS)
            v = *(const float2*)&in[((((size_t)b * Ci + ci) * Hi + yi) * Wi + xi) * T_STEPS + t];
        sm2[flat] = v;
    }
    __syncthreads();

    int tx = threadIdx.x;
    int t  = t0 + 2 * tx;
    int item = threadIdx.y;
    int co0 = (item / XG) * COB;
    int xo0 = (item % XG) * XR;

    float2 acc[COB][XR];
#pragma unroll
    for (int j = 0; j < COB; j++)
#pragma unroll
        for (int r = 0; r < XR; r++) acc[j][r] = make_float2(0.0f, 0.0f);

    for (int ci = 0; ci < Ci; ci++) {
#pragma unroll
        for (int ky = 0; ky < K; ky++) {
            // input window (shared across all COB channels)
            float2 v[K + XR - 1];
            const float2* sp = &sm2[((ci * K + ky) * WT + xo0) * TP + tx];
#pragma unroll
            for (int j = 0; j < K + XR - 1; j++) v[j] = sp[j * TP];
            // weights for this (ci,ky) row, broadcast-packed
            float2 wv[COB][K];
#pragma unroll
            for (int j = 0; j < COB; j++)
#pragma unroll
                for (int kx = 0; kx < K; kx++) {
                    float w0 = w[(((co0 + j) * Ci + ci) * K + ky) * K + kx];
                    wv[j][kx] = make_float2(w0, w0);
                }
            // accumulate: per-output order stays (ci, ky, kx) ascending -> exact
#pragma unroll
            for (int kx = 0; kx < K; kx++)
#pragma unroll
                for (int j = 0; j < COB; j++)
#pragma unroll
                    for (int r = 0; r < XR; r++)
                        ffma2(acc[j][r], v[kx + r], wv[j][kx]);
        }
    }

    if (t < T_STEPS) {
#pragma unroll
        for (int j = 0; j < COB; j++)
#pragma unroll
            for (int r = 0; r < XR; r++)
                *(float2*)&out[((((size_t)b * Co + co0 + j) * Ho + yo) * Wo + xo0 + r) * T_STEPS + t]
                    = acc[j][r];
    }
}

// ---------------- spike: one thread per neuron, sequential over T ----------------
__global__ void spike_kernel(const float* __restrict__ u, float* __restrict__ s, int nNeurons)
{
    int n = blockIdx.x * blockDim.x + threadIdx.x;
    if (n >= nNeurons) return;
    const float4* up = (const float4*)(u + (size_t)n * T_STEPS);
    float4*       sp = (float4*)(s + (size_t)n * T_STEPS);
    float buf[10];
#pragma unroll
    for (int j = 0; j < 10; j++) buf[j] = 0.0f;
    for (int q = 0; q < T_STEPS / 4; q++) {
        float4 uv = up[q];
        float4 ev;
        ev.x = spike_step(uv.x, buf);
        ev.y = spike_step(uv.y, buf);
        ev.z = spike_step(uv.z, buf);
        ev.w = spike_step(uv.w, buf);
        sp[q] = ev;
    }
}

// ---------------- fused 2x2 sum-pool (x 1.1*theta) + spike ----------------
__global__ void poolspike_kernel(const float* __restrict__ sin, float* __restrict__ sout,
                                 int C, int Ho, int Wo)
{
    int n = blockIdx.x * blockDim.x + threadIdx.x;
    int total = 8 * C * Ho * Wo;
    if (n >= total) return;
    int x  = n % Wo;
    int y  = (n / Wo) % Ho;
    int cb = n / (Wo * Ho);       // b*C + c

    size_t rowT = (size_t)(2 * Wo) * T_STEPS;
    size_t base = (((size_t)cb * (2 * Ho) + 2 * y) * (2 * Wo) + 2 * x) * T_STEPS;
    const float4* p00 = (const float4*)(sin + base);
    const float4* p01 = (const float4*)(sin + base + T_STEPS);
    const float4* p10 = (const float4*)(sin + base + rowT);
    const float4* p11 = (const float4*)(sin + base + rowT + T_STEPS);
    float4* sp = (float4*)(sout + (size_t)n * T_STEPS);

    float buf[10];
#pragma unroll
    for (int j = 0; j < 10; j++) buf[j] = 0.0f;

    for (int q = 0; q < T_STEPS / 4; q++) {
        float4 a = p00[q], b4 = p01[q], c4 = p10[q], d4 = p11[q];
        float4 ev;
        ev.x = spike_step(11.0f * (a.x + b4.x + c4.x + d4.x), buf);
        ev.y = spike_step(11.0f * (a.y + b4.y + c4.y + d4.y), buf);
        ev.z = spike_step(11.0f * (a.z + b4.z + c4.z + d4.z), buf);
        ev.w = spike_step(11.0f * (a.w + b4.w + c4.w + d4.w), buf);
        sp[q] = ev;
    }
}

// ---------------- FC (full-spatial contraction) + final spike ----------------
__global__ void fc_spike_kernel(const float* __restrict__ s5, const float* __restrict__ wfc,
                                float* __restrict__ out)
{
    int b = blockIdx.x / 10;
    int o = blockIdx.x % 10;
    __shared__ float u_sm[304];
    __shared__ float psum[8][33];
    int tx = threadIdx.x;   // 32
    int ty = threadIdx.y;   // 8

    const float* sb = s5 + (size_t)b * 4096 * T_STEPS;
    const float* wo = wfc + o * 4096;

    for (int t0 = 0; t0 < T_STEPS; t0 += 32) {
        int t = t0 + tx;
        float acc = 0.0f;
        if (t < T_STEPS) {
            int c0 = ty * 512;
            for (int c = c0; c < c0 + 512; c++)
                acc = fmaf(sb[(size_t)c * T_STEPS + t], wo[c], acc);
        }
        psum[ty][tx] = acc;
        __syncthreads();
        if (ty == 0 && t < T_STEPS) {
            float v = psum[0][tx];
#pragma unroll
            for (int j = 1; j < 8; j++) v += psum[j][tx];
            u_sm[t] = v;
        }
        __syncthreads();
    }

    if (tx == 0 && ty == 0) {
        float buf[10];
#pragma unroll
        for (int j = 0; j < 10; j++) buf[j] = 0.0f;
        float* op = out + (size_t)(b * 10 + o) * T_STEPS;
        for (int t = 0; t < T_STEPS; t++)
            op[t] = spike_step(u_sm[t], buf);
    }
}

// ---------------- launcher ----------------
extern "C" void kernel_launch(void* const* d_in, const int* in_sizes, int n_in,
                              void* d_out, int out_size)
{
    const float* x   = (const float*)d_in[0];   // [8,2,34,34,300]
    const float* w1  = (const float*)d_in[1];   // [16,2,5,5]
    const float* w2  = (const float*)d_in[2];   // [32,16,3,3]
    const float* w3  = (const float*)d_in[3];   // [64,32,3,3]
    const float* wfc = (const float*)d_in[4];   // [10,64,8,8]
    float* out = (float*)d_out;                 // [8,10,1,1,300]

    float *A = nullptr, *B = nullptr;
    cudaGetSymbolAddress((void**)&A, g_bufA);
    cudaGetSymbolAddress((void**)&B, g_bufB);

    // smem bytes: Ci*K*WT*TP * sizeof(float2)
    constexpr int SM1 = 2  * 5 * 36 * TP * 8;   //  46080
    constexpr int SM2 = 16 * 3 * 18 * TP * 8;   // 110592
    constexpr int SM3 = 32 * 3 * 10 * TP * 8;   // 122880

    cudaFuncSetAttribute(conv_kernel<2,34,34,16,32,32,5,1>,
                         cudaFuncAttributeMaxDynamicSharedMemorySize, SM1);
    cudaFuncSetAttribute(conv_kernel<16,16,16,32,16,16,3,1>,
                         cudaFuncAttributeMaxDynamicSharedMemorySize, SM2);
    cudaFuncSetAttribute(conv_kernel<32,8,8,64,8,8,3,1>,
                         cudaFuncAttributeMaxDynamicSharedMemorySize, SM3);

    dim3 cb(16, 16);
    // L1: conv 2->16 5x5 pad1 : x -> A (u1)  [8,16,32,32,300]
    conv_kernel<2,34,34,16,32,32,5,1><<<8 * 32 * NTC, cb, SM1>>>(x, w1, A);
    // spike1: A -> B (s1)
    spike_kernel<<<131072 / 256, 256>>>(A, B, 131072);
    // pool+spike2: B -> A (s2) [8,16,16,16,300]
    poolspike_kernel<<<32768 / 256, 256>>>(B, A, 16, 16, 16);
    // L2: conv 16->32 3x3 pad1 : A -> B (u3) [8,32,16,16,300]
    conv_kernel<16,16,16,32,16,16,3,1><<<8 * 16 * NTC, cb, SM2>>>(A, w2, B);
    // spike3: B -> A (s3)
    spike_kernel<<<65536 / 256, 256>>>(B, A, 65536);
    // pool+spike4: A -> B (s4) [8,32,8,8,300]
    poolspike_kernel<<<16384 / 256, 256>>>(A, B, 32, 8, 8);
    // L3: conv 32->64 3x3 pad1 : B -> A (u5) [8,64,8,8,300]
    conv_kernel<32,8,8,64,8,8,3,1><<<8 * 8 * NTC, cb, SM3>>>(B, w3, A);
    // spike5: A -> B (s5)
    spike_kernel<<<32768 / 256, 256>>>(A, B, 32768);
    // FC + final spike: B -> out
    fc_spike_kernel<<<80, dim3(32, 8)>>>(B, wfc, out);
}

// round 6
// speedup vs baseline: 1.2456x; 1.0627x over previous
#include <cuda_runtime.h>
#include <cstddef>

#define T_STEPS 300
#define THETA 10.0f

// ---------------- scratch (ping-pong) ----------------
__device__ float g_bufA[39321600];   // max needed: 8*16*32*32*300
__device__ float g_bufB[39321600];

// REF_KERNEL[1..10]: -20*t*exp(1-t), t=1..10 (fp32-rounded from double)
__constant__ float c_refk[10] = {
    -20.0f,
    -14.715177646857693f,
    -8.1201169941967624f,
    -3.9829654694291156f,
    -1.8315638888734179f,
    -0.80855363989025606f,
    -0.34702530473329019f,
    -0.14590111448872260f,
    -0.060383273022452132f,
    -0.024681960817335913f
};

__device__ __forceinline__ float spike_step(float u, float (&buf)[10]) {
    float um = u + buf[0];
    float e = (um >= THETA) ? 1.0f : 0.0f;
#pragma unroll
    for (int j = 0; j < 9; j++) buf[j] = buf[j + 1] + e * c_refk[j];
    buf[9] = e * c_refk[9];
    return e;   // TS = 1 -> amplitude 1
}

// packed 2x fp32 fma (Blackwell FFMA2). Bit-identical to two fmaf's.
__device__ __forceinline__ void ffma2(float2& c, float2 a, float2 b) {
    unsigned long long au = *reinterpret_cast<unsigned long long*>(&a);
    unsigned long long bu = *reinterpret_cast<unsigned long long*>(&b);
    unsigned long long cu = *reinterpret_cast<unsigned long long*>(&c);
    asm("fma.rn.f32x2 %0, %1, %2, %0;" : "+l"(cu) : "l"(au), "l"(bu));
    *reinterpret_cast<unsigned long long*>(&c) = cu;
}

// ---------------- conv (per-timestep 2D conv, T innermost, f32x2 packed) -------
// block: (b, yo, t-chunk of 2*TP steps). threads (TP, NTY).
// tx owns timestep pair (t0+2tx, t0+2tx+1); ty loops over (co-group, xo-group)
// items. Each item computes COB=4 output channels x XR=4 x-positions: each smem
// window load feeds COB*K FMAs, while acc regs stay small (32) so 2 CTAs/SM fit.
template <int Ci, int Hi, int Wi, int Co, int Ho, int Wo, int K, int PAD,
          int TP, int NTY>
__global__ void __launch_bounds__(TP * NTY, 2)
conv_kernel(const float* __restrict__ in, const float* __restrict__ w,
            float* __restrict__ out)
{
    constexpr int WT  = Wo + K - 1;
    constexpr int XR  = 4;
    constexpr int COB = 4;
    constexpr int XG  = Wo / XR;
    constexpr int CG  = Co / COB;
    constexpr int NITEM = XG * CG;
    constexpr int TCH = 2 * TP;
    constexpr int NTC = (T_STEPS + TCH - 1) / TCH;
    constexpr int NTH = TP * NTY;

    extern __shared__ char smraw[];
    float2* sm2 = (float2*)smraw;

    int bid = blockIdx.x;
    int tc  = bid % NTC;
    int yo  = (bid / NTC) % Ho;
    int b   = bid / (NTC * Ho);
    int t0  = tc * TCH;

    int tid = threadIdx.y * TP + threadIdx.x;

    // ---- load padded input tile as float2 pairs: [Ci][K][WT][TP] ----
    constexpr int TILE2 = Ci * K * WT * TP;
    for (int flat = tid; flat < TILE2; flat += NTH) {
        int tt = flat % TP;
        int r  = flat / TP;
        int xw = r % WT; r /= WT;
        int ky = r % K;
        int ci = r / K;
        int xi = xw - PAD;
        int yi = yo - PAD + ky;
        int t  = t0 + 2 * tt;
        float2 v = make_float2(0.0f, 0.0f);
        if (xi >= 0 && xi < Wi && yi >= 0 && yi < Hi && t < T_STEPS)
            v = *(const float2*)&in[((((size_t)b * Ci + ci) * Hi + yi) * Wi + xi) * T_STEPS + t];
        sm2[flat] = v;
    }
    __syncthreads();

    int tx = threadIdx.x;
    int t  = t0 + 2 * tx;

    for (int item = threadIdx.y; item < NITEM; item += NTY) {
        int co0 = (item / XG) * COB;
        int xo0 = (item % XG) * XR;

        float2 acc[COB][XR];
#pragma unroll
        for (int j = 0; j < COB; j++)
#pragma unroll
            for (int r = 0; r < XR; r++) acc[j][r] = make_float2(0.0f, 0.0f);

        for (int ci = 0; ci < Ci; ci++) {
#pragma unroll
            for (int ky = 0; ky < K; ky++) {
                // input window (shared across all COB channels)
                float2 v[K + XR - 1];
                const float2* sp = &sm2[((ci * K + ky) * WT + xo0) * TP + tx];
#pragma unroll
                for (int j = 0; j < K + XR - 1; j++) v[j] = sp[j * TP];
                // weights for this (ci,ky) row, broadcast-packed
                float2 wv[COB][K];
#pragma unroll
                for (int j = 0; j < COB; j++)
#pragma unroll
                    for (int kx = 0; kx < K; kx++) {
                        float w0 = w[(((co0 + j) * Ci + ci) * K + ky) * K + kx];
                        wv[j][kx] = make_float2(w0, w0);
                    }
                // accumulate: per-output order stays (ci, ky, kx) ascending -> exact
#pragma unroll
                for (int kx = 0; kx < K; kx++)
#pragma unroll
                    for (int j = 0; j < COB; j++)
#pragma unroll
                        for (int r = 0; r < XR; r++)
                            ffma2(acc[j][r], v[kx + r], wv[j][kx]);
            }
        }

        if (t < T_STEPS) {
#pragma unroll
            for (int j = 0; j < COB; j++)
#pragma unroll
                for (int r = 0; r < XR; r++)
                    *(float2*)&out[((((size_t)b * Co + co0 + j) * Ho + yo) * Wo + xo0 + r) * T_STEPS + t]
                        = acc[j][r];
        }
    }
}

// ---------------- spike: one thread per neuron, sequential over T ----------------
__global__ void spike_kernel(const float* __restrict__ u, float* __restrict__ s, int nNeurons)
{
    int n = blockIdx.x * blockDim.x + threadIdx.x;
    if (n >= nNeurons) return;
    const float4* up = (const float4*)(u + (size_t)n * T_STEPS);
    float4*       sp = (float4*)(s + (size_t)n * T_STEPS);
    float buf[10];
#pragma unroll
    for (int j = 0; j < 10; j++) buf[j] = 0.0f;
    for (int q = 0; q < T_STEPS / 4; q++) {
        float4 uv = up[q];
        float4 ev;
        ev.x = spike_step(uv.x, buf);
        ev.y = spike_step(uv.y, buf);
        ev.z = spike_step(uv.z, buf);
        ev.w = spike_step(uv.w, buf);
        sp[q] = ev;
    }
}

// ---------------- fused 2x2 sum-pool (x 1.1*theta) + spike ----------------
__global__ void poolspike_kernel(const float* __restrict__ sin, float* __restrict__ sout,
                                 int C, int Ho, int Wo)
{
    int n = blockIdx.x * blockDim.x + threadIdx.x;
    int total = 8 * C * Ho * Wo;
    if (n >= total) return;
    int x  = n % Wo;
    int y  = (n / Wo) % Ho;
    int cb = n / (Wo * Ho);       // b*C + c

    size_t rowT = (size_t)(2 * Wo) * T_STEPS;
    size_t base = (((size_t)cb * (2 * Ho) + 2 * y) * (2 * Wo) + 2 * x) * T_STEPS;
    const float4* p00 = (const float4*)(sin + base);
    const float4* p01 = (const float4*)(sin + base + T_STEPS);
    const float4* p10 = (const float4*)(sin + base + rowT);
    const float4* p11 = (const float4*)(sin + base + rowT + T_STEPS);
    float4* sp = (float4*)(sout + (size_t)n * T_STEPS);

    float buf[10];
#pragma unroll
    for (int j = 0; j < 10; j++) buf[j] = 0.0f;

    for (int q = 0; q < T_STEPS / 4; q++) {
        float4 a = p00[q], b4 = p01[q], c4 = p10[q], d4 = p11[q];
        float4 ev;
        ev.x = spike_step(11.0f * (a.x + b4.x + c4.x + d4.x), buf);
        ev.y = spike_step(11.0f * (a.y + b4.y + c4.y + d4.y), buf);
        ev.z = spike_step(11.0f * (a.z + b4.z + c4.z + d4.z), buf);
        ev.w = spike_step(11.0f * (a.w + b4.w + c4.w + d4.w), buf);
        sp[q] = ev;
    }
}

// ---------------- FC (full-spatial contraction) + final spike ----------------
__global__ void fc_spike_kernel(const float* __restrict__ s5, const float* __restrict__ wfc,
                                float* __restrict__ out)
{
    int b = blockIdx.x / 10;
    int o = blockIdx.x % 10;
    __shared__ float u_sm[304];
    __shared__ float psum[8][33];
    int tx = threadIdx.x;   // 32
    int ty = threadIdx.y;   // 8

    const float* sb = s5 + (size_t)b * 4096 * T_STEPS;
    const float* wo = wfc + o * 4096;

    for (int t0 = 0; t0 < T_STEPS; t0 += 32) {
        int t = t0 + tx;
        float acc = 0.0f;
        if (t < T_STEPS) {
            int c0 = ty * 512;
            for (int c = c0; c < c0 + 512; c++)
                acc = fmaf(sb[(size_t)c * T_STEPS + t], wo[c], acc);
        }
        psum[ty][tx] = acc;
        __syncthreads();
        if (ty == 0 && t < T_STEPS) {
            float v = psum[0][tx];
#pragma unroll
            for (int j = 1; j < 8; j++) v += psum[j][tx];
            u_sm[t] = v;
        }
        __syncthreads();
    }

    if (tx == 0 && ty == 0) {
        float buf[10];
#pragma unroll
        for (int j = 0; j < 10; j++) buf[j] = 0.0f;
        float* op = out + (size_t)(b * 10 + o) * T_STEPS;
        for (int t = 0; t < T_STEPS; t++)
            op[t] = spike_step(u_sm[t], buf);
    }
}

// ---------------- launcher ----------------
extern "C" void kernel_launch(void* const* d_in, const int* in_sizes, int n_in,
                              void* d_out, int out_size)
{
    const float* x   = (const float*)d_in[0];   // [8,2,34,34,300]
    const float* w1  = (const float*)d_in[1];   // [16,2,5,5]
    const float* w2  = (const float*)d_in[2];   // [32,16,3,3]
    const float* w3  = (const float*)d_in[3];   // [64,32,3,3]
    const float* wfc = (const float*)d_in[4];   // [10,64,8,8]
    float* out = (float*)d_out;                 // [8,10,1,1,300]

    float *A = nullptr, *B = nullptr;
    cudaGetSymbolAddress((void**)&A, g_bufA);
    cudaGetSymbolAddress((void**)&B, g_bufB);

    // smem bytes: Ci*K*WT*TP * sizeof(float2)
    constexpr int SM1 = 2  * 5 * 36 * 16 * 8;   //  46080   (TP=16)
    constexpr int SM2 = 16 * 3 * 18 * 16 * 8;   // 110592   (TP=16)
    constexpr int SM3 = 32 * 3 * 10 * 12 * 8;   //  92160   (TP=12)

    cudaFuncSetAttribute(conv_kernel<2,34,34,16,32,32,5,1,16,16>,
                         cudaFuncAttributeMaxDynamicSharedMemorySize, SM1);
    cudaFuncSetAttribute(conv_kernel<16,16,16,32,16,16,3,1,16,16>,
                         cudaFuncAttributeMaxDynamicSharedMemorySize, SM2);
    cudaFuncSetAttribute(conv_kernel<32,8,8,64,8,8,3,1,12,16>,
                         cudaFuncAttributeMaxDynamicSharedMemorySize, SM3);

    // NTC: ceil(300 / (2*TP))
    constexpr int NTC16 = 10;   // TP=16 -> 32-step chunks
    constexpr int NTC12 = 13;   // TP=12 -> 24-step chunks

    // L1: conv 2->16 5x5 pad1 : x -> A (u1)  [8,16,32,32,300]
    conv_kernel<2,34,34,16,32,32,5,1,16,16><<<8 * 32 * NTC16, dim3(16, 16), SM1>>>(x, w1, A);
    // spike1: A -> B (s1)
    spike_kernel<<<131072 / 256, 256>>>(A, B, 131072);
    // pool+spike2: B -> A (s2) [8,16,16,16,300]
    poolspike_kernel<<<32768 / 256, 256>>>(B, A, 16, 16, 16);
    // L2: conv 16->32 3x3 pad1 : A -> B (u3) [8,32,16,16,300]
    conv_kernel<16,16,16,32,16,16,3,1,16,16><<<8 * 16 * NTC16, dim3(16, 16), SM2>>>(A, w2, B);
    // spike3: B -> A (s3)
    spike_kernel<<<65536 / 256, 256>>>(B, A, 65536);
    // pool+spike4: A -> B (s4) [8,32,8,8,300]
    poolspike_kernel<<<16384 / 256, 256>>>(A, B, 32, 8, 8);
    // L3: conv 32->64 3x3 pad1 : B -> A (u5) [8,64,8,8,300]
    conv_kernel<32,8,8,64,8,8,3,1,12,16><<<8 * 8 * NTC12, dim3(12, 16), SM3>>>(B, w3, A);
    // spike5: A -> B (s5)
    spike_kernel<<<32768 / 256, 256>>>(A, B, 32768);
    // FC + final spike: B -> out
    fc_spike_kernel<<<80, dim3(32, 8)>>>(B, wfc, out);
}

// round 7
// speedup vs baseline: 2.1950x; 1.7622x over previous
#include <cuda_runtime.h>
#include <cstddef>

#define T_STEPS 300
#define THETA 10.0f

// ---------------- scratch (ping-pong) ----------------
__device__ float g_bufA[39321600];   // max needed: 8*16*32*32*300
__device__ float g_bufB[39321600];

// REF_KERNEL[1..10]: -20*t*exp(1-t), t=1..10 (fp32-rounded from double)
__constant__ float c_refk[10] = {
    -20.0f,
    -14.715177646857693f,
    -8.1201169941967624f,
    -3.9829654694291156f,
    -1.8315638888734179f,
    -0.80855363989025606f,
    -0.34702530473329019f,
    -0.14590111448872260f,
    -0.060383273022452132f,
    -0.024681960817335913f
};

__device__ __forceinline__ float spike_step(float u, float (&buf)[10]) {
    float um = u + buf[0];
    float e = (um >= THETA) ? 1.0f : 0.0f;
#pragma unroll
    for (int j = 0; j < 9; j++) buf[j] = buf[j + 1] + e * c_refk[j];
    buf[9] = e * c_refk[9];
    return e;   // TS = 1 -> amplitude 1
}

// packed 2x fp32 fma (Blackwell FFMA2). Bit-identical to two fmaf's.
__device__ __forceinline__ void ffma2(float2& c, float2 a, float2 b) {
    unsigned long long au = *reinterpret_cast<unsigned long long*>(&a);
    unsigned long long bu = *reinterpret_cast<unsigned long long*>(&b);
    unsigned long long cu = *reinterpret_cast<unsigned long long*>(&c);
    asm("fma.rn.f32x2 %0, %1, %2, %0;" : "+l"(cu) : "l"(au), "l"(bu));
    *reinterpret_cast<unsigned long long*>(&c) = cu;
}

// float4 MAC with scalar weight = 2x FFMA2; bit-identical per lane to fmaf.
__device__ __forceinline__ void ffma4(float4& c, const float4& a, float w) {
    float2 wv = make_float2(w, w);
    float2 clo = make_float2(c.x, c.y), chi = make_float2(c.z, c.w);
    ffma2(clo, make_float2(a.x, a.y), wv);
    ffma2(chi, make_float2(a.z, a.w), wv);
    c.x = clo.x; c.y = clo.y; c.z = chi.x; c.w = chi.y;
}

// ---------------- conv (per-timestep 2D conv, T innermost, float4 over time) ---
// block: (b, yo, t-chunk of 4*TPQ steps). threads (TPQ, 32).
// tx owns one timestep quad; ty owns exactly one (co-group, xo-group) item:
// COB=4 output channels x XR=4 x-positions. Each smem window load (LDS.128)
// feeds COB*K*2 FFMA2, so fma dominates the issue mix.
template <int Ci, int Hi, int Wi, int Co, int Ho, int Wo, int K, int PAD, int TPQ>
__global__ void __launch_bounds__(TPQ * 32, 2)
conv_kernel(const float* __restrict__ in, const float* __restrict__ w,
            float* __restrict__ out)
{
    constexpr int WT  = Wo + K - 1;
    constexpr int XR  = 4;
    constexpr int COB = 4;
    constexpr int XG  = Wo / XR;
    constexpr int CG  = Co / COB;
    static_assert(XG * CG == 32, "one item per ty");
    constexpr int TCH = 4 * TPQ;
    constexpr int NTC = (T_STEPS + TCH - 1) / TCH;
    constexpr int NTH = TPQ * 32;

    extern __shared__ char smraw[];
    float4* sm4 = (float4*)smraw;

    int bid = blockIdx.x;
    int tc  = bid % NTC;
    int yo  = (bid / NTC) % Ho;
    int b   = bid / (NTC * Ho);
    int t0  = tc * TCH;

    int tid = threadIdx.y * TPQ + threadIdx.x;

    // ---- load padded input tile as float4 quads: [Ci][K][WT][TPQ] ----
    constexpr int TILE4 = Ci * K * WT * TPQ;
    for (int flat = tid; flat < TILE4; flat += NTH) {
        int tt = flat % TPQ;
        int r  = flat / TPQ;
        int xw = r % WT; r /= WT;
        int ky = r % K;
        int ci = r / K;
        int xi = xw - PAD;
        int yi = yo - PAD + ky;
        int t  = t0 + 4 * tt;
        float4 v = make_float4(0.0f, 0.0f, 0.0f, 0.0f);
        if (xi >= 0 && xi < Wi && yi >= 0 && yi < Hi && t < T_STEPS)
            v = *(const float4*)&in[((((size_t)b * Ci + ci) * Hi + yi) * Wi + xi) * T_STEPS + t];
        sm4[flat] = v;
    }
    __syncthreads();

    int tx = threadIdx.x;
    int t  = t0 + 4 * tx;
    int item = threadIdx.y;
    int co0 = (item / XG) * COB;
    int xo0 = (item % XG) * XR;

    float4 acc[COB][XR];
#pragma unroll
    for (int j = 0; j < COB; j++)
#pragma unroll
        for (int r = 0; r < XR; r++) acc[j][r] = make_float4(0.0f, 0.0f, 0.0f, 0.0f);

    for (int ci = 0; ci < Ci; ci++) {
#pragma unroll
        for (int ky = 0; ky < K; ky++) {
            // input window (shared across all COB channels)
            float4 v[K + XR - 1];
            const float4* sp = &sm4[((ci * K + ky) * WT + xo0) * TPQ + tx];
#pragma unroll
            for (int j = 0; j < K + XR - 1; j++) v[j] = sp[j * TPQ];
            // weights for this (ci,ky) row
            float wv[COB][K];
#pragma unroll
            for (int j = 0; j < COB; j++)
#pragma unroll
                for (int kx = 0; kx < K; kx++)
                    wv[j][kx] = __ldg(&w[(((co0 + j) * Ci + ci) * K + ky) * K + kx]);
            // accumulate: per-output order stays (ci, ky, kx) ascending -> exact
#pragma unroll
            for (int kx = 0; kx < K; kx++)
#pragma unroll
                for (int j = 0; j < COB; j++)
#pragma unroll
                    for (int r = 0; r < XR; r++)
                        ffma4(acc[j][r], v[kx + r], wv[j][kx]);
        }
    }

    if (t < T_STEPS) {
#pragma unroll
        for (int j = 0; j < COB; j++)
#pragma unroll
            for (int r = 0; r < XR; r++)
                *(float4*)&out[((((size_t)b * Co + co0 + j) * Ho + yo) * Wo + xo0 + r) * T_STEPS + t]
                    = acc[j][r];
    }
}

// ---------------- spike: one thread per neuron, sequential over T ----------------
__global__ void spike_kernel(const float* __restrict__ u, float* __restrict__ s, int nNeurons)
{
    int n = blockIdx.x * blockDim.x + threadIdx.x;
    if (n >= nNeurons) return;
    const float4* up = (const float4*)(u + (size_t)n * T_STEPS);
    float4*       sp = (float4*)(s + (size_t)n * T_STEPS);
    float buf[10];
#pragma unroll
    for (int j = 0; j < 10; j++) buf[j] = 0.0f;
    for (int q = 0; q < T_STEPS / 4; q++) {
        float4 uv = up[q];
        float4 ev;
        ev.x = spike_step(uv.x, buf);
        ev.y = spike_step(uv.y, buf);
        ev.z = spike_step(uv.z, buf);
        ev.w = spike_step(uv.w, buf);
        sp[q] = ev;
    }
}

// ---------------- fused 2x2 sum-pool (x 1.1*theta) + spike ----------------
__global__ void poolspike_kernel(const float* __restrict__ sin, float* __restrict__ sout,
                                 int C, int Ho, int Wo)
{
    int n = blockIdx.x * blockDim.x + threadIdx.x;
    int total = 8 * C * Ho * Wo;
    if (n >= total) return;
    int x  = n % Wo;
    int y  = (n / Wo) % Ho;
    int cb = n / (Wo * Ho);       // b*C + c

    size_t rowT = (size_t)(2 * Wo) * T_STEPS;
    size_t base = (((size_t)cb * (2 * Ho) + 2 * y) * (2 * Wo) + 2 * x) * T_STEPS;
    const float4* p00 = (const float4*)(sin + base);
    const float4* p01 = (const float4*)(sin + base + T_STEPS);
    const float4* p10 = (const float4*)(sin + base + rowT);
    const float4* p11 = (const float4*)(sin + base + rowT + T_STEPS);
    float4* sp = (float4*)(sout + (size_t)n * T_STEPS);

    float buf[10];
#pragma unroll
    for (int j = 0; j < 10; j++) buf[j] = 0.0f;

    for (int q = 0; q < T_STEPS / 4; q++) {
        float4 a = p00[q], b4 = p01[q], c4 = p10[q], d4 = p11[q];
        float4 ev;
        ev.x = spike_step(11.0f * (a.x + b4.x + c4.x + d4.x), buf);
        ev.y = spike_step(11.0f * (a.y + b4.y + c4.y + d4.y), buf);
        ev.z = spike_step(11.0f * (a.z + b4.z + c4.z + d4.z), buf);
        ev.w = spike_step(11.0f * (a.w + b4.w + c4.w + d4.w), buf);
        sp[q] = ev;
    }
}

// ---------------- FC: block = (b, t-quad); s5 chunk staged in smem ----------------
// s5: [8, 4096, 300], wfc: [10, 4096], u_out: [8, 10, 300]
// 320 threads: warp w computes output o=w via 128-c strided partial + butterfly.
__global__ void __launch_bounds__(320, 3)
fc_kernel(const float* __restrict__ s5, const float* __restrict__ wfc,
          float* __restrict__ u_out)
{
    constexpr int NQ = T_STEPS / 4;   // 75
    int q = blockIdx.x % NQ;
    int b = blockIdx.x / NQ;
    int t0 = q * 4;

    extern __shared__ float4 s_sm[];  // [4096]
    int tid = threadIdx.y * 32 + threadIdx.x;

    const float* sb = s5 + (size_t)b * 4096 * T_STEPS + t0;
    for (int c = tid; c < 4096; c += 320)
        s_sm[c] = *(const float4*)&sb[(size_t)c * T_STEPS];
    __syncthreads();

    int o    = threadIdx.y;   // 0..9
    int lane = threadIdx.x;   // 0..31
    const float* wo = wfc + o * 4096;

    float4 acc = make_float4(0.0f, 0.0f, 0.0f, 0.0f);
    for (int c = lane; c < 4096; c += 32) {
        float4 v = s_sm[c];
        float wgt = __ldg(&wo[c]);
        acc.x = fmaf(v.x, wgt, acc.x);
        acc.y = fmaf(v.y, wgt, acc.y);
        acc.z = fmaf(v.z, wgt, acc.z);
        acc.w = fmaf(v.w, wgt, acc.w);
    }
#pragma unroll
    for (int d = 16; d >= 1; d >>= 1) {
        acc.x += __shfl_xor_sync(0xffffffffu, acc.x, d);
        acc.y += __shfl_xor_sync(0xffffffffu, acc.y, d);
        acc.z += __shfl_xor_sync(0xffffffffu, acc.z, d);
        acc.w += __shfl_xor_sync(0xffffffffu, acc.w, d);
    }
    if (lane == 0)
        *(float4*)&u_out[(size_t)(b * 10 + o) * T_STEPS + t0] = acc;
}

// ---------------- final spike on 80 neurons ----------------
__global__ void spike_final_kernel(const float* __restrict__ u, float* __restrict__ out)
{
    int n = threadIdx.x;
    if (n >= 80) return;
    const float4* up = (const float4*)(u + (size_t)n * T_STEPS);
    float4*       sp = (float4*)(out + (size_t)n * T_STEPS);
    float buf[10];
#pragma unroll
    for (int j = 0; j < 10; j++) buf[j] = 0.0f;
    for (int q = 0; q < T_STEPS / 4; q++) {
        float4 uv = up[q];
        float4 ev;
        ev.x = spike_step(uv.x, buf);
        ev.y = spike_step(uv.y, buf);
        ev.z = spike_step(uv.z, buf);
        ev.w = spike_step(uv.w, buf);
        sp[q] = ev;
    }
}

// ---------------- launcher ----------------
extern "C" void kernel_launch(void* const* d_in, const int* in_sizes, int n_in,
                              void* d_out, int out_size)
{
    const float* x   = (const float*)d_in[0];   // [8,2,34,34,300]
    const float* w1  = (const float*)d_in[1];   // [16,2,5,5]
    const float* w2  = (const float*)d_in[2];   // [32,16,3,3]
    const float* w3  = (const float*)d_in[3];   // [64,32,3,3]
    const float* wfc = (const float*)d_in[4];   // [10,64,8,8]
    float* out = (float*)d_out;                 // [8,10,1,1,300]

    float *A = nullptr, *B = nullptr;
    cudaGetSymbolAddress((void**)&A, g_bufA);
    cudaGetSymbolAddress((void**)&B, g_bufB);

    // smem bytes: Ci*K*WT*TPQ * sizeof(float4)
    constexpr int SM1 = 2  * 5 * 36 * 8 * 16;   //  46080  (TPQ=8, 32-step chunks)
    constexpr int SM2 = 16 * 3 * 18 * 8 * 16;   // 110592  (TPQ=8)
    constexpr int SM3 = 32 * 3 * 10 * 6 * 16;   //  92160  (TPQ=6, 24-step chunks)
    constexpr int SMF = 4096 * 16;              //  65536  (FC chunk)

    cudaFuncSetAttribute(conv_kernel<2,34,34,16,32,32,5,1,8>,
                         cudaFuncAttributeMaxDynamicSharedMemorySize, SM1);
    cudaFuncSetAttribute(conv_kernel<16,16,16,32,16,16,3,1,8>,
                         cudaFuncAttributeMaxDynamicSharedMemorySize, SM2);
    cudaFuncSetAttribute(conv_kernel<32,8,8,64,8,8,3,1,6>,
                         cudaFuncAttributeMaxDynamicSharedMemorySize, SM3);
    cudaFuncSetAttribute(fc_kernel,
                         cudaFuncAttributeMaxDynamicSharedMemorySize, SMF);

    constexpr int NTC8 = 10;   // ceil(300/32)
    constexpr int NTC6 = 13;   // ceil(300/24)

    // L1: conv 2->16 5x5 pad1 : x -> A (u1)  [8,16,32,32,300]
    conv_kernel<2,34,34,16,32,32,5,1,8><<<8 * 32 * NTC8, dim3(8, 32), SM1>>>(x, w1, A);
    // spike1: A -> B (s1)
    spike_kernel<<<131072 / 256, 256>>>(A, B, 131072);
    // pool+spike2: B -> A (s2) [8,16,16,16,300]
    poolspike_kernel<<<32768 / 256, 256>>>(B, A, 16, 16, 16);
    // L2: conv 16->32 3x3 pad1 : A -> B (u3) [8,32,16,16,300]
    conv_kernel<16,16,16,32,16,16,3,1,8><<<8 * 16 * NTC8, dim3(8, 32), SM2>>>(A, w2, B);
    // spike3: B -> A (s3)
    spike_kernel<<<65536 / 256, 256>>>(B, A, 65536);
    // pool+spike4: A -> B (s4) [8,32,8,8,300]
    poolspike_kernel<<<16384 / 256, 256>>>(A, B, 32, 8, 8);
    // L3: conv 32->64 3x3 pad1 : B -> A (u5) [8,64,8,8,300]
    conv_kernel<32,8,8,64,8,8,3,1,6><<<8 * 8 * NTC6, dim3(6, 32), SM3>>>(B, w3, A);
    // spike5: A -> B (s5)
    spike_kernel<<<32768 / 256, 256>>>(A, B, 32768);
    // FC: B (s5) -> A (u6) [8,10,300]
    fc_kernel<<<8 * 75, dim3(32, 10), SMF>>>(B, wfc, A);
    // final spike: A -> out
    spike_final_kernel<<<1, 96>>>(A, out);
}

// round 9
// speedup vs baseline: 2.5605x; 1.1665x over previous
#include <cuda_runtime.h>
#include <cstddef>

#define T_STEPS 300
#define TS_U8   304          // padded stride for u8 spike tensors (16B aligned)
#define THETA 10.0f

// ---------------- scratch ----------------
__device__ float g_bufA[39321600];          // float u scratch (max 157MB)
__device__ unsigned char g_bufS[9961472];   // u8 spike scratch (32768 * 304)

// REF_KERNEL[1..10]: -20*t*exp(1-t), t=1..10 (fp32-rounded from double)
__constant__ float c_refk[10] = {
    -20.0f,
    -14.715177646857693f,
    -8.1201169941967624f,
    -3.9829654694291156f,
    -1.8315638888734179f,
    -0.80855363989025606f,
    -0.34702530473329019f,
    -0.14590111448872260f,
    -0.060383273022452132f,
    -0.024681960817335913f
};

__device__ __forceinline__ float spike_step(float u, float (&buf)[10]) {
    float um = u + buf[0];
    float e = (um >= THETA) ? 1.0f : 0.0f;
#pragma unroll
    for (int j = 0; j < 9; j++) buf[j] = buf[j + 1] + e * c_refk[j];
    buf[9] = e * c_refk[9];
    return e;   // TS = 1 -> amplitude 1
}

// packed 2x fp32 fma (Blackwell FFMA2). Bit-identical to two fmaf's.
__device__ __forceinline__ void ffma2(float2& c, float2 a, float2 b) {
    unsigned long long au = *reinterpret_cast<unsigned long long*>(&a);
    unsigned long long bu = *reinterpret_cast<unsigned long long*>(&b);
    unsigned long long cu = *reinterpret_cast<unsigned long long*>(&c);
    asm("fma.rn.f32x2 %0, %1, %2, %0;" : "+l"(cu) : "l"(au), "l"(bu));
    *reinterpret_cast<unsigned long long*>(&c) = cu;
}

// float4 MAC with scalar weight = 2x FFMA2; bit-identical per lane to fmaf.
__device__ __forceinline__ void ffma4(float4& c, const float4& a, float w) {
    float2 wv = make_float2(w, w);
    float2 clo = make_float2(c.x, c.y), chi = make_float2(c.z, c.w);
    ffma2(clo, make_float2(a.x, a.y), wv);
    ffma2(chi, make_float2(a.z, a.w), wv);
    c.x = clo.x; c.y = clo.y; c.z = chi.x; c.w = chi.y;
}

// typed quad loaders (u8 spikes are exactly 0/1 -> conversion exact)
__device__ __forceinline__ float4 load_quad(const float* p) {
    return *(const float4*)p;
}
__device__ __forceinline__ float4 load_quad(const unsigned char* p) {
    uchar4 c = *(const uchar4*)p;
    return make_float4((float)c.x, (float)c.y, (float)c.z, (float)c.w);
}

// ---------------- conv (per-timestep 2D conv, T innermost, float4 over time) ---
// block: (b, yo, t-chunk of 4*TPQ steps). threads (TPQ, 32).
// tx owns one timestep quad; ty owns one (co-group, xo-group) item:
// COB=4 output channels x XR=4 x-positions.
template <typename IT, int IN_TS,
          int Ci, int Hi, int Wi, int Co, int Ho, int Wo, int K, int PAD, int TPQ>
__global__ void __launch_bounds__(TPQ * 32, 2)
conv_kernel(const IT* __restrict__ in, const float* __restrict__ w,
            float* __restrict__ out)
{
    constexpr int WT  = Wo + K - 1;
    constexpr int XR  = 4;
    constexpr int COB = 4;
    constexpr int XG  = Wo / XR;
    constexpr int CG  = Co / COB;
    static_assert(XG * CG == 32, "one item per ty");
    constexpr int TCH = 4 * TPQ;
    constexpr int NTC = (T_STEPS + TCH - 1) / TCH;
    constexpr int NTH = TPQ * 32;

    extern __shared__ char smraw[];
    float4* sm4 = (float4*)smraw;

    int bid = blockIdx.x;
    int tc  = bid % NTC;
    int yo  = (bid / NTC) % Ho;
    int b   = bid / (NTC * Ho);
    int t0  = tc * TCH;

    int tid = threadIdx.y * TPQ + threadIdx.x;

    // ---- load padded input tile as float4 quads: [Ci][K][WT][TPQ] ----
    constexpr int TILE4 = Ci * K * WT * TPQ;
    for (int flat = tid; flat < TILE4; flat += NTH) {
        int tt = flat % TPQ;
        int r  = flat / TPQ;
        int xw = r % WT; r /= WT;
        int ky = r % K;
        int ci = r / K;
        int xi = xw - PAD;
        int yi = yo - PAD + ky;
        int t  = t0 + 4 * tt;
        float4 v = make_float4(0.0f, 0.0f, 0.0f, 0.0f);
        if (xi >= 0 && xi < Wi && yi >= 0 && yi < Hi && t < T_STEPS)
            v = load_quad(&in[((((size_t)b * Ci + ci) * Hi + yi) * Wi + xi) * IN_TS + t]);
        sm4[flat] = v;
    }
    __syncthreads();

    int tx = threadIdx.x;
    int t  = t0 + 4 * tx;
    int item = threadIdx.y;
    int co0 = (item / XG) * COB;
    int xo0 = (item % XG) * XR;

    float4 acc[COB][XR];
#pragma unroll
    for (int j = 0; j < COB; j++)
#pragma unroll
        for (int r = 0; r < XR; r++) acc[j][r] = make_float4(0.0f, 0.0f, 0.0f, 0.0f);

    for (int ci = 0; ci < Ci; ci++) {
#pragma unroll
        for (int ky = 0; ky < K; ky++) {
            // input window (shared across all COB channels)
            float4 v[K + XR - 1];
            const float4* sp = &sm4[((ci * K + ky) * WT + xo0) * TPQ + tx];
#pragma unroll
            for (int j = 0; j < K + XR - 1; j++) v[j] = sp[j * TPQ];
            // weights for this (ci,ky) row
            float wv[COB][K];
#pragma unroll
            for (int j = 0; j < COB; j++)
#pragma unroll
                for (int kx = 0; kx < K; kx++)
                    wv[j][kx] = __ldg(&w[(((co0 + j) * Ci + ci) * K + ky) * K + kx]);
            // accumulate: per-output order stays (ci, ky, kx) ascending -> exact
#pragma unroll
            for (int kx = 0; kx < K; kx++)
#pragma unroll
                for (int j = 0; j < COB; j++)
#pragma unroll
                    for (int r = 0; r < XR; r++)
                        ffma4(acc[j][r], v[kx + r], wv[j][kx]);
        }
    }

    if (t < T_STEPS) {
#pragma unroll
        for (int j = 0; j < COB; j++)
#pragma unroll
            for (int r = 0; r < XR; r++)
                *(float4*)&out[((((size_t)b * Co + co0 + j) * Ho + yo) * Wo + xo0 + r) * T_STEPS + t]
                    = acc[j][r];
    }
}

// ---------------- fused spike -> 2x2 sum-pool (x11) -> spike, u8 out ----------
// One thread = one pooled neuron: runs the 4 parent refractory recurrences AND
// the pooled recurrence; parent spikes (s1/s3) are never written to memory.
// u: [8, C, 2Ho, 2Wo, 300] float ; s: [8*C*Ho*Wo, 304] u8
__global__ void spikepool_kernel(const float* __restrict__ u, unsigned char* __restrict__ s,
                                 int C, int Ho, int Wo)
{
    int n = blockIdx.x * blockDim.x + threadIdx.x;
    int total = 8 * C * Ho * Wo;
    if (n >= total) return;
    int x  = n % Wo;
    int y  = (n / Wo) % Ho;
    int cb = n / (Wo * Ho);       // b*C + c

    size_t rowT = (size_t)(2 * Wo) * T_STEPS;
    size_t base = (((size_t)cb * (2 * Ho) + 2 * y) * (2 * Wo) + 2 * x) * T_STEPS;
    const float4* p00 = (const float4*)(u + base);
    const float4* p01 = (const float4*)(u + base + T_STEPS);
    const float4* p10 = (const float4*)(u + base + rowT);
    const float4* p11 = (const float4*)(u + base + rowT + T_STEPS);
    unsigned char* sp = s + (size_t)n * TS_U8;

    float b00[10], b01[10], b10[10], b11[10], bp[10];
#pragma unroll
    for (int j = 0; j < 10; j++) { b00[j]=0.f; b01[j]=0.f; b10[j]=0.f; b11[j]=0.f; bp[j]=0.f; }

    unsigned int wbuf[4];
    for (int q = 0; q < T_STEPS / 4; q++) {
        float4 a = p00[q], b4 = p01[q], c4 = p10[q], d4 = p11[q];
        float s0 = spike_step(a.x, b00) + spike_step(b4.x, b01)
                 + spike_step(c4.x, b10) + spike_step(d4.x, b11);
        float s1 = spike_step(a.y, b00) + spike_step(b4.y, b01)
                 + spike_step(c4.y, b10) + spike_step(d4.y, b11);
        float s2v = spike_step(a.z, b00) + spike_step(b4.z, b01)
                 + spike_step(c4.z, b10) + spike_step(d4.z, b11);
        float s3 = spike_step(a.w, b00) + spike_step(b4.w, b01)
                 + spike_step(c4.w, b10) + spike_step(d4.w, b11);
        unsigned int e0 = (unsigned int)spike_step(11.0f * s0, bp);
        unsigned int e1 = (unsigned int)spike_step(11.0f * s1, bp);
        unsigned int e2 = (unsigned int)spike_step(11.0f * s2v, bp);
        unsigned int e3 = (unsigned int)spike_step(11.0f * s3, bp);
        wbuf[q & 3] = e0 | (e1 << 8) | (e2 << 16) | (e3 << 24);
        if ((q & 3) == 3)
            ((uint4*)sp)[q >> 2] = *(uint4*)wbuf;
    }
    // tail: quads 72..74 unflushed
#pragma unroll
    for (int i = 0; i < 3; i++)
        ((unsigned int*)sp)[72 + i] = wbuf[i];
}

// ---------------- spike with u8 output (layer 5) ----------------
__global__ void spike_u8_kernel(const float* __restrict__ u, unsigned char* __restrict__ s,
                                int nNeurons)
{
    int n = blockIdx.x * blockDim.x + threadIdx.x;
    if (n >= nNeurons) return;
    const float4* up = (const float4*)(u + (size_t)n * T_STEPS);
    unsigned char* sp = s + (size_t)n * TS_U8;
    float buf[10];
#pragma unroll
    for (int j = 0; j < 10; j++) buf[j] = 0.0f;
    unsigned int wbuf[4];
    for (int q = 0; q < T_STEPS / 4; q++) {
        float4 uv = up[q];
        unsigned int e0 = (unsigned int)spike_step(uv.x, buf);
        unsigned int e1 = (unsigned int)spike_step(uv.y, buf);
        unsigned int e2 = (unsigned int)spike_step(uv.z, buf);
        unsigned int e3 = (unsigned int)spike_step(uv.w, buf);
        wbuf[q & 3] = e0 | (e1 << 8) | (e2 << 16) | (e3 << 24);
        if ((q & 3) == 3)
            ((uint4*)sp)[q >> 2] = *(uint4*)wbuf;
    }
#pragma unroll
    for (int i = 0; i < 3; i++)
        ((unsigned int*)sp)[72 + i] = wbuf[i];
}

// ---------------- FC: block = (b, t-quad); s5 chunk staged in smem --------------
// s5: [8*4096, 304] u8, wfc: [10, 4096], u_out: [8, 10, 300]
__global__ void __launch_bounds__(320, 3)
fc_kernel(const unsigned char* __restrict__ s5, const float* __restrict__ wfc,
          float* __restrict__ u_out)
{
    constexpr int NQ = T_STEPS / 4;   // 75
    int q = blockIdx.x % NQ;
    int b = blockIdx.x / NQ;
    int t0 = q * 4;

    extern __shared__ float4 s_sm[];  // [4096]
    int tid = threadIdx.y * 32 + threadIdx.x;

    const unsigned char* sb = s5 + (size_t)b * 4096 * TS_U8 + t0;
    for (int c = tid; c < 4096; c += 320) {
        uchar4 cc = *(const uchar4*)&sb[(size_t)c * TS_U8];
        s_sm[c] = make_float4((float)cc.x, (float)cc.y, (float)cc.z, (float)cc.w);
    }
    __syncthreads();

    int o    = threadIdx.y;   // 0..9
    int lane = threadIdx.x;   // 0..31
    const float* wo = wfc + o * 4096;

    float4 acc = make_float4(0.0f, 0.0f, 0.0f, 0.0f);
    for (int c = lane; c < 4096; c += 32) {
        float4 v = s_sm[c];
        float wgt = __ldg(&wo[c]);
        acc.x = fmaf(v.x, wgt, acc.x);
        acc.y = fmaf(v.y, wgt, acc.y);
        acc.z = fmaf(v.z, wgt, acc.z);
        acc.w = fmaf(v.w, wgt, acc.w);
    }
#pragma unroll
    for (int d = 16; d >= 1; d >>= 1) {
        acc.x += __shfl_xor_sync(0xffffffffu, acc.x, d);
        acc.y += __shfl_xor_sync(0xffffffffu, acc.y, d);
        acc.z += __shfl_xor_sync(0xffffffffu, acc.z, d);
        acc.w += __shfl_xor_sync(0xffffffffu, acc.w, d);
    }
    if (lane == 0)
        *(float4*)&u_out[(size_t)(b * 10 + o) * T_STEPS + t0] = acc;
}

// ---------------- final spike on 80 neurons ----------------
__global__ void spike_final_kernel(const float* __restrict__ u, float* __restrict__ out)
{
    int n = threadIdx.x;
    if (n >= 80) return;
    const float4* up = (const float4*)(u + (size_t)n * T_STEPS);
    float4*       sp = (float4*)(out + (size_t)n * T_STEPS);
    float buf[10];
#pragma unroll
    for (int j = 0; j < 10; j++) buf[j] = 0.0f;
    for (int q = 0; q < T_STEPS / 4; q++) {
        float4 uv = up[q];
        float4 ev;
        ev.x = spike_step(uv.x, buf);
        ev.y = spike_step(uv.y, buf);
        ev.z = spike_step(uv.z, buf);
        ev.w = spike_step(uv.w, buf);
        sp[q] = ev;
    }
}

// ---------------- launcher ----------------
extern "C" void kernel_launch(void* const* d_in, const int* in_sizes, int n_in,
                              void* d_out, int out_size)
{
    const float* x   = (const float*)d_in[0];   // [8,2,34,34,300]
    const float* w1  = (const float*)d_in[1];   // [16,2,5,5]
    const float* w2  = (const float*)d_in[2];   // [32,16,3,3]
    const float* w3  = (const float*)d_in[3];   // [64,32,3,3]
    const float* wfc = (const float*)d_in[4];   // [10,64,8,8]
    float* out = (float*)d_out;                 // [8,10,1,1,300]

    float *A = nullptr;
    unsigned char *S = nullptr;
    cudaGetSymbolAddress((void**)&A, g_bufA);
    cudaGetSymbolAddress((void**)&S, g_bufS);

    // smem bytes: Ci*K*WT*TPQ * sizeof(float4)
    constexpr int SM1 = 2  * 5 * 36 * 8 * 16;   //  46080  (TPQ=8, 32-step chunks)
    constexpr int SM2 = 16 * 3 * 18 * 8 * 16;   // 110592  (TPQ=8)
    constexpr int SM3 = 32 * 3 * 10 * 6 * 16;   //  92160  (TPQ=6, 24-step chunks)
    constexpr int SMF = 4096 * 16;              //  65536  (FC chunk)

    cudaFuncSetAttribute((const void*)conv_kernel<float,T_STEPS,2,34,34,16,32,32,5,1,8>,
                         cudaFuncAttributeMaxDynamicSharedMemorySize, SM1);
    cudaFuncSetAttribute((const void*)conv_kernel<unsigned char,TS_U8,16,16,16,32,16,16,3,1,8>,
                         cudaFuncAttributeMaxDynamicSharedMemorySize, SM2);
    cudaFuncSetAttribute((const void*)conv_kernel<unsigned char,TS_U8,32,8,8,64,8,8,3,1,6>,
                         cudaFuncAttributeMaxDynamicSharedMemorySize, SM3);
    cudaFuncSetAttribute((const void*)fc_kernel,
                         cudaFuncAttributeMaxDynamicSharedMemorySize, SMF);

    constexpr int NTC8 = 10;   // ceil(300/32)
    constexpr int NTC6 = 13;   // ceil(300/24)

    // L1: conv 2->16 5x5 pad1 : x -> A (u1)  [8,16,32,32,300]
    conv_kernel<float,T_STEPS,2,34,34,16,32,32,5,1,8>
        <<<8 * 32 * NTC8, dim3(8, 32), SM1>>>(x, w1, A);
    // spike1 + pool + spike2 fused: A -> S (s2, u8) [8*16*16*16, 304]
    spikepool_kernel<<<32768 / 256, 256>>>(A, S, 16, 16, 16);
    // L2: conv 16->32 3x3 pad1 : S -> A (u3) [8,32,16,16,300]
    conv_kernel<unsigned char,TS_U8,16,16,16,32,16,16,3,1,8>
        <<<8 * 16 * NTC8, dim3(8, 32), SM2>>>(S, w2, A);
    // spike3 + pool + spike4 fused: A -> S (s4, u8) [8*32*8*8, 304]
    spikepool_kernel<<<16384 / 256, 256>>>(A, S, 32, 8, 8);
    // L3: conv 32->64 3x3 pad1 : S -> A (u5) [8,64,8,8,300]
    conv_kernel<unsigned char,TS_U8,32,8,8,64,8,8,3,1,6>
        <<<8 * 8 * NTC6, dim3(6, 32), SM3>>>(S, w3, A);
    // spike5: A -> S (s5, u8)
    spike_u8_kernel<<<32768 / 256, 256>>>(A, S, 32768);
    // FC: S (s5) -> A (u6) [8,10,300]
    fc_kernel<<<8 * 75, dim3(32, 10), SMF>>>(S, wfc, A);
    // final spike: A -> out
    spike_final_kernel<<<1, 96>>>(A, out);
}

// round 10
// speedup vs baseline: 3.0618x; 1.1958x over previous
#include <cuda_runtime.h>
#include <cstddef>

#define T_STEPS 300
#define TS_U8   304          // padded stride for u8 spike tensors (16B aligned)
#define THETA 10.0f

// ---------------- scratch ----------------
__device__ float g_bufA[39321600];          // float u scratch (max 157MB)
__device__ unsigned char g_bufS[9961472];   // u8 spike scratch (32768 * 304)

// REF_KERNEL[1..10]: -20*t*exp(1-t), t=1..10 (fp32-rounded from double)
__constant__ float c_refk[10] = {
    -20.0f,
    -14.715177646857693f,
    -8.1201169941967624f,
    -3.9829654694291156f,
    -1.8315638888734179f,
    -0.80855363989025606f,
    -0.34702530473329019f,
    -0.14590111448872260f,
    -0.060383273022452132f,
    -0.024681960817335913f
};

__device__ __forceinline__ float spike_step(float u, float (&buf)[10]) {
    float um = u + buf[0];
    float e = (um >= THETA) ? 1.0f : 0.0f;
#pragma unroll
    for (int j = 0; j < 9; j++) buf[j] = buf[j + 1] + e * c_refk[j];
    buf[9] = e * c_refk[9];
    return e;   // TS = 1 -> amplitude 1
}

// packed 2x fp32 fma (Blackwell FFMA2). Bit-identical to two fmaf's.
__device__ __forceinline__ void ffma2(float2& c, float2 a, float2 b) {
    unsigned long long au = *reinterpret_cast<unsigned long long*>(&a);
    unsigned long long bu = *reinterpret_cast<unsigned long long*>(&b);
    unsigned long long cu = *reinterpret_cast<unsigned long long*>(&c);
    asm("fma.rn.f32x2 %0, %1, %2, %0;" : "+l"(cu) : "l"(au), "l"(bu));
    *reinterpret_cast<unsigned long long*>(&c) = cu;
}

// float4 MAC with scalar weight = 2x FFMA2; bit-identical per lane to fmaf.
__device__ __forceinline__ void ffma4(float4& c, const float4& a, float w) {
    float2 wv = make_float2(w, w);
    float2 clo = make_float2(c.x, c.y), chi = make_float2(c.z, c.w);
    ffma2(clo, make_float2(a.x, a.y), wv);
    ffma2(chi, make_float2(a.z, a.w), wv);
    c.x = clo.x; c.y = clo.y; c.z = chi.x; c.w = chi.y;
}

// typed quad loaders (u8 spikes are exactly 0/1 -> conversion exact)
__device__ __forceinline__ float4 load_quad(const float* p) {
    return *(const float4*)p;
}
__device__ __forceinline__ float4 load_quad(const unsigned char* p) {
    uchar4 c = *(const uchar4*)p;
    return make_float4((float)c.x, (float)c.y, (float)c.z, (float)c.w);
}

// ---------------- conv (per-timestep 2D conv, T innermost, float4 over time) ---
// block: (b, yo, t-chunk of 4*TPQ steps). threads (TPQ, 32).
// tx owns one timestep quad; ty owns one (co-group, xo-group) item:
// COB=4 output channels x XR=4 x-positions.
template <typename IT, int IN_TS,
          int Ci, int Hi, int Wi, int Co, int Ho, int Wo, int K, int PAD, int TPQ>
__global__ void __launch_bounds__(TPQ * 32, 2)
conv_kernel(const IT* __restrict__ in, const float* __restrict__ w,
            float* __restrict__ out)
{
    constexpr int WT  = Wo + K - 1;
    constexpr int XR  = 4;
    constexpr int COB = 4;
    constexpr int XG  = Wo / XR;
    constexpr int CG  = Co / COB;
    static_assert(XG * CG == 32, "one item per ty");
    constexpr int TCH = 4 * TPQ;
    constexpr int NTC = (T_STEPS + TCH - 1) / TCH;
    constexpr int NTH = TPQ * 32;

    extern __shared__ char smraw[];
    float4* sm4 = (float4*)smraw;

    int bid = blockIdx.x;
    int tc  = bid % NTC;
    int yo  = (bid / NTC) % Ho;
    int b   = bid / (NTC * Ho);
    int t0  = tc * TCH;

    int tid = threadIdx.y * TPQ + threadIdx.x;

    // ---- load padded input tile as float4 quads: [Ci][K][WT][TPQ] ----
    constexpr int TILE4 = Ci * K * WT * TPQ;
    for (int flat = tid; flat < TILE4; flat += NTH) {
        int tt = flat % TPQ;
        int r  = flat / TPQ;
        int xw = r % WT; r /= WT;
        int ky = r % K;
        int ci = r / K;
        int xi = xw - PAD;
        int yi = yo - PAD + ky;
        int t  = t0 + 4 * tt;
        float4 v = make_float4(0.0f, 0.0f, 0.0f, 0.0f);
        if (xi >= 0 && xi < Wi && yi >= 0 && yi < Hi && t < T_STEPS)
            v = load_quad(&in[((((size_t)b * Ci + ci) * Hi + yi) * Wi + xi) * IN_TS + t]);
        sm4[flat] = v;
    }
    __syncthreads();

    int tx = threadIdx.x;
    int t  = t0 + 4 * tx;
    int item = threadIdx.y;
    int co0 = (item / XG) * COB;
    int xo0 = (item % XG) * XR;

    float4 acc[COB][XR];
#pragma unroll
    for (int j = 0; j < COB; j++)
#pragma unroll
        for (int r = 0; r < XR; r++) acc[j][r] = make_float4(0.0f, 0.0f, 0.0f, 0.0f);

    for (int ci = 0; ci < Ci; ci++) {
#pragma unroll
        for (int ky = 0; ky < K; ky++) {
            // input window (shared across all COB channels)
            float4 v[K + XR - 1];
            const float4* sp = &sm4[((ci * K + ky) * WT + xo0) * TPQ + tx];
#pragma unroll
            for (int j = 0; j < K + XR - 1; j++) v[j] = sp[j * TPQ];
            // weights for this (ci,ky) row
            float wv[COB][K];
#pragma unroll
            for (int j = 0; j < COB; j++)
#pragma unroll
                for (int kx = 0; kx < K; kx++)
                    wv[j][kx] = __ldg(&w[(((co0 + j) * Ci + ci) * K + ky) * K + kx]);
            // accumulate: per-output order stays (ci, ky, kx) ascending -> exact
#pragma unroll
            for (int kx = 0; kx < K; kx++)
#pragma unroll
                for (int j = 0; j < COB; j++)
#pragma unroll
                    for (int r = 0; r < XR; r++)
                        ffma4(acc[j][r], v[kx + r], wv[j][kx]);
        }
    }

    if (t < T_STEPS) {
#pragma unroll
        for (int j = 0; j < COB; j++)
#pragma unroll
            for (int r = 0; r < XR; r++)
                *(float4*)&out[((((size_t)b * Co + co0 + j) * Ho + yo) * Wo + xo0 + r) * T_STEPS + t]
                    = acc[j][r];
    }
}

// ---------------- fused spike -> 2x2 sum-pool (x11) -> spike, u8 out ----------
// WARP-COOPERATIVE: 4 lanes per pooled neuron. Each lane runs ONE parent
// refractory recurrence on its own contiguous row; parent spikes are summed
// across the 4-lane group via shfl butterfly; all 4 lanes redundantly run the
// pooled recurrence (bit-identical), lane sub==0 writes the u8 spikes.
__device__ __forceinline__ unsigned int pool_quad(float4 uv, float (&bufp)[10],
                                                  float (&bp)[10]) {
    float p0 = spike_step(uv.x, bufp);
    float p1 = spike_step(uv.y, bufp);
    float p2 = spike_step(uv.z, bufp);
    float p3 = spike_step(uv.w, bufp);
    p0 += __shfl_xor_sync(0xffffffffu, p0, 1); p0 += __shfl_xor_sync(0xffffffffu, p0, 2);
    p1 += __shfl_xor_sync(0xffffffffu, p1, 1); p1 += __shfl_xor_sync(0xffffffffu, p1, 2);
    p2 += __shfl_xor_sync(0xffffffffu, p2, 1); p2 += __shfl_xor_sync(0xffffffffu, p2, 2);
    p3 += __shfl_xor_sync(0xffffffffu, p3, 1); p3 += __shfl_xor_sync(0xffffffffu, p3, 2);
    unsigned int e0 = (unsigned int)spike_step(11.0f * p0, bp);
    unsigned int e1 = (unsigned int)spike_step(11.0f * p1, bp);
    unsigned int e2 = (unsigned int)spike_step(11.0f * p2, bp);
    unsigned int e3 = (unsigned int)spike_step(11.0f * p3, bp);
    return e0 | (e1 << 8) | (e2 << 16) | (e3 << 24);
}

__global__ void __launch_bounds__(256)
spikepool_kernel(const float* __restrict__ u, unsigned char* __restrict__ s,
                 int C, int Ho, int Wo)
{
    int idx = blockIdx.x * blockDim.x + threadIdx.x;
    int sub = idx & 3;        // which parent (dy = sub>>1, dx = sub&1)
    int n   = idx >> 2;       // pooled neuron
    int total = 8 * C * Ho * Wo;
    if (n >= total) return;
    int x  = n % Wo;
    int y  = (n / Wo) % Ho;
    int cb = n / (Wo * Ho);   // b*C + c

    int dy = sub >> 1, dx = sub & 1;
    size_t base = (((size_t)cb * (2 * Ho) + 2 * y + dy) * (2 * Wo) + 2 * x + dx) * T_STEPS;
    const float4* up = (const float4*)(u + base);
    unsigned char* sp = s + (size_t)n * TS_U8;

    float bufp[10], bp[10];
#pragma unroll
    for (int j = 0; j < 10; j++) { bufp[j] = 0.0f; bp[j] = 0.0f; }

    // 16-step pipelined iterations: 4 independent loads in flight
    for (int g = 0; g < 18; g++) {
        float4 v[4];
#pragma unroll
        for (int i = 0; i < 4; i++) v[i] = up[g * 4 + i];
        unsigned int wd[4];
#pragma unroll
        for (int i = 0; i < 4; i++) wd[i] = pool_quad(v[i], bufp, bp);
        if (sub == 0)
            ((uint4*)sp)[g] = make_uint4(wd[0], wd[1], wd[2], wd[3]);
    }
    // tail: 3 quads (t=288..299)
    {
        float4 v[3];
#pragma unroll
        for (int i = 0; i < 3; i++) v[i] = up[72 + i];
#pragma unroll
        for (int i = 0; i < 3; i++) {
            unsigned int wd = pool_quad(v[i], bufp, bp);
            if (sub == 0) ((unsigned int*)sp)[72 + i] = wd;
        }
    }
}

// ---------------- spike with u8 output (layer 5), 16-step pipelined ----------
__global__ void __launch_bounds__(256)
spike_u8_kernel(const float* __restrict__ u, unsigned char* __restrict__ s, int nNeurons)
{
    int n = blockIdx.x * blockDim.x + threadIdx.x;
    if (n >= nNeurons) return;
    const float4* up = (const float4*)(u + (size_t)n * T_STEPS);
    unsigned char* sp = s + (size_t)n * TS_U8;
    float buf[10];
#pragma unroll
    for (int j = 0; j < 10; j++) buf[j] = 0.0f;

    for (int g = 0; g < 18; g++) {
        float4 v[4];
#pragma unroll
        for (int i = 0; i < 4; i++) v[i] = up[g * 4 + i];
        unsigned int wd[4];
#pragma unroll
        for (int i = 0; i < 4; i++) {
            unsigned int e0 = (unsigned int)spike_step(v[i].x, buf);
            unsigned int e1 = (unsigned int)spike_step(v[i].y, buf);
            unsigned int e2 = (unsigned int)spike_step(v[i].z, buf);
            unsigned int e3 = (unsigned int)spike_step(v[i].w, buf);
            wd[i] = e0 | (e1 << 8) | (e2 << 16) | (e3 << 24);
        }
        ((uint4*)sp)[g] = make_uint4(wd[0], wd[1], wd[2], wd[3]);
    }
    {
        float4 v[3];
#pragma unroll
        for (int i = 0; i < 3; i++) v[i] = up[72 + i];
#pragma unroll
        for (int i = 0; i < 3; i++) {
            unsigned int e0 = (unsigned int)spike_step(v[i].x, buf);
            unsigned int e1 = (unsigned int)spike_step(v[i].y, buf);
            unsigned int e2 = (unsigned int)spike_step(v[i].z, buf);
            unsigned int e3 = (unsigned int)spike_step(v[i].w, buf);
            ((unsigned int*)sp)[72 + i] = e0 | (e1 << 8) | (e2 << 16) | (e3 << 24);
        }
    }
}

// ---------------- FC: block = (b, t-quad); s5 chunk staged in smem --------------
// s5: [8*4096, 304] u8, wfc: [10, 4096], u_out: [8, 10, 300]
__global__ void __launch_bounds__(320, 3)
fc_kernel(const unsigned char* __restrict__ s5, const float* __restrict__ wfc,
          float* __restrict__ u_out)
{
    constexpr int NQ = T_STEPS / 4;   // 75
    int q = blockIdx.x % NQ;
    int b = blockIdx.x / NQ;
    int t0 = q * 4;

    extern __shared__ float4 s_sm[];  // [4096]
    int tid = threadIdx.y * 32 + threadIdx.x;

    const unsigned char* sb = s5 + (size_t)b * 4096 * TS_U8 + t0;
    for (int c = tid; c < 4096; c += 320) {
        uchar4 cc = *(const uchar4*)&sb[(size_t)c * TS_U8];
        s_sm[c] = make_float4((float)cc.x, (float)cc.y, (float)cc.z, (float)cc.w);
    }
    __syncthreads();

    int o    = threadIdx.y;   // 0..9
    int lane = threadIdx.x;   // 0..31
    const float* wo = wfc + o * 4096;

    float4 acc = make_float4(0.0f, 0.0f, 0.0f, 0.0f);
    for (int c = lane; c < 4096; c += 32) {
        float4 v = s_sm[c];
        float wgt = __ldg(&wo[c]);
        acc.x = fmaf(v.x, wgt, acc.x);
        acc.y = fmaf(v.y, wgt, acc.y);
        acc.z = fmaf(v.z, wgt, acc.z);
        acc.w = fmaf(v.w, wgt, acc.w);
    }
#pragma unroll
    for (int d = 16; d >= 1; d >>= 1) {
        acc.x += __shfl_xor_sync(0xffffffffu, acc.x, d);
        acc.y += __shfl_xor_sync(0xffffffffu, acc.y, d);
        acc.z += __shfl_xor_sync(0xffffffffu, acc.z, d);
        acc.w += __shfl_xor_sync(0xffffffffu, acc.w, d);
    }
    if (lane == 0)
        *(float4*)&u_out[(size_t)(b * 10 + o) * T_STEPS + t0] = acc;
}

// ---------------- final spike on 80 neurons ----------------
__global__ void spike_final_kernel(const float* __restrict__ u, float* __restrict__ out)
{
    int n = threadIdx.x;
    if (n >= 80) return;
    const float4* up = (const float4*)(u + (size_t)n * T_STEPS);
    float4*       sp = (float4*)(out + (size_t)n * T_STEPS);
    float buf[10];
#pragma unroll
    for (int j = 0; j < 10; j++) buf[j] = 0.0f;
    for (int q = 0; q < T_STEPS / 4; q++) {
        float4 uv = up[q];
        float4 ev;
        ev.x = spike_step(uv.x, buf);
        ev.y = spike_step(uv.y, buf);
        ev.z = spike_step(uv.z, buf);
        ev.w = spike_step(uv.w, buf);
        sp[q] = ev;
    }
}

// ---------------- launcher ----------------
extern "C" void kernel_launch(void* const* d_in, const int* in_sizes, int n_in,
                              void* d_out, int out_size)
{
    const float* x   = (const float*)d_in[0];   // [8,2,34,34,300]
    const float* w1  = (const float*)d_in[1];   // [16,2,5,5]
    const float* w2  = (const float*)d_in[2];   // [32,16,3,3]
    const float* w3  = (const float*)d_in[3];   // [64,32,3,3]
    const float* wfc = (const float*)d_in[4];   // [10,64,8,8]
    float* out = (float*)d_out;                 // [8,10,1,1,300]

    float *A = nullptr;
    unsigned char *S = nullptr;
    cudaGetSymbolAddress((void**)&A, g_bufA);
    cudaGetSymbolAddress((void**)&S, g_bufS);

    // smem bytes: Ci*K*WT*TPQ * sizeof(float4)
    constexpr int SM1 = 2  * 5 * 36 * 8 * 16;   //  46080  (TPQ=8, 32-step chunks)
    constexpr int SM2 = 16 * 3 * 18 * 8 * 16;   // 110592  (TPQ=8)
    constexpr int SM3 = 32 * 3 * 10 * 6 * 16;   //  92160  (TPQ=6, 24-step chunks)
    constexpr int SMF = 4096 * 16;              //  65536  (FC chunk)

    cudaFuncSetAttribute((const void*)conv_kernel<float,T_STEPS,2,34,34,16,32,32,5,1,8>,
                         cudaFuncAttributeMaxDynamicSharedMemorySize, SM1);
    cudaFuncSetAttribute((const void*)conv_kernel<unsigned char,TS_U8,16,16,16,32,16,16,3,1,8>,
                         cudaFuncAttributeMaxDynamicSharedMemorySize, SM2);
    cudaFuncSetAttribute((const void*)conv_kernel<unsigned char,TS_U8,32,8,8,64,8,8,3,1,6>,
                         cudaFuncAttributeMaxDynamicSharedMemorySize, SM3);
    cudaFuncSetAttribute((const void*)fc_kernel,
                         cudaFuncAttributeMaxDynamicSharedMemorySize, SMF);

    constexpr int NTC8 = 10;   // ceil(300/32)
    constexpr int NTC6 = 13;   // ceil(300/24)

    // L1: conv 2->16 5x5 pad1 : x -> A (u1)  [8,16,32,32,300]
    conv_kernel<float,T_STEPS,2,34,34,16,32,32,5,1,8>
        <<<8 * 32 * NTC8, dim3(8, 32), SM1>>>(x, w1, A);
    // spike1 + pool + spike2 fused (4 lanes/neuron): A -> S (s2, u8)
    spikepool_kernel<<<(32768 * 4) / 256, 256>>>(A, S, 16, 16, 16);
    // L2: conv 16->32 3x3 pad1 : S -> A (u3) [8,32,16,16,300]
    conv_kernel<unsigned char,TS_U8,16,16,16,32,16,16,3,1,8>
        <<<8 * 16 * NTC8, dim3(8, 32), SM2>>>(S, w2, A);
    // spike3 + pool + spike4 fused (4 lanes/neuron): A -> S (s4, u8)
    spikepool_kernel<<<(16384 * 4) / 256, 256>>>(A, S, 32, 8, 8);
    // L3: conv 32->64 3x3 pad1 : S -> A (u5) [8,64,8,8,300]
    conv_kernel<unsigned char,TS_U8,32,8,8,64,8,8,3,1,6>
        <<<8 * 8 * NTC6, dim3(6, 32), SM3>>>(S, w3, A);
    // spike5: A -> S (s5, u8)
    spike_u8_kernel<<<32768 / 256, 256>>>(A, S, 32768);
    // FC: S (s5) -> A (u6) [8,10,300]
    fc_kernel<<<8 * 75, dim3(32, 10), SMF>>>(S, wfc, A);
    // final spike: A -> out
    spike_final_kernel<<<1, 96>>>(A, out);
}

// round 11
// speedup vs baseline: 3.1447x; 1.0271x over previous
#include <cuda_runtime.h>
#include <cstddef>

#define T_STEPS 300
#define TS_U8   304          // padded stride for u8 spike tensors (16B aligned)
#define THETA 10.0f

// ---------------- scratch ----------------
__device__ float g_bufA[39321600];          // float u scratch (max 157MB)
__device__ unsigned char g_bufS[9961472];   // u8 spike / u8 input scratch
__device__ float g_bufW[32000];             // packed weights (w1:1280, w2:6144, w3:24576)

#define W1_OFF 0
#define W2_OFF 1280
#define W3_OFF 7424

// REF_KERNEL[1..10]: -20*t*exp(1-t), t=1..10 (fp32-rounded from double)
__constant__ float c_refk[10] = {
    -20.0f,
    -14.715177646857693f,
    -8.1201169941967624f,
    -3.9829654694291156f,
    -1.8315638888734179f,
    -0.80855363989025606f,
    -0.34702530473329019f,
    -0.14590111448872260f,
    -0.060383273022452132f,
    -0.024681960817335913f
};

__device__ __forceinline__ float spike_step(float u, float (&buf)[10]) {
    float um = u + buf[0];
    float e = (um >= THETA) ? 1.0f : 0.0f;
#pragma unroll
    for (int j = 0; j < 9; j++) buf[j] = buf[j + 1] + e * c_refk[j];
    buf[9] = e * c_refk[9];
    return e;   // TS = 1 -> amplitude 1
}

// packed 2x fp32 fma (Blackwell FFMA2). Bit-identical to two fmaf's.
__device__ __forceinline__ void ffma2(float2& c, float2 a, float2 b) {
    unsigned long long au = *reinterpret_cast<unsigned long long*>(&a);
    unsigned long long bu = *reinterpret_cast<unsigned long long*>(&b);
    unsigned long long cu = *reinterpret_cast<unsigned long long*>(&c);
    asm("fma.rn.f32x2 %0, %1, %2, %0;" : "+l"(cu) : "l"(au), "l"(bu));
    *reinterpret_cast<unsigned long long*>(&c) = cu;
}

// float4 MAC with scalar weight = 2x FFMA2; bit-identical per lane to fmaf.
__device__ __forceinline__ void ffma4(float4& c, const float4& a, float w) {
    float2 wv = make_float2(w, w);
    float2 clo = make_float2(c.x, c.y), chi = make_float2(c.z, c.w);
    ffma2(clo, make_float2(a.x, a.y), wv);
    ffma2(chi, make_float2(a.z, a.w), wv);
    c.x = clo.x; c.y = clo.y; c.z = chi.x; c.w = chi.y;
}

__device__ __forceinline__ float f4_get(const float4& v, int i) {
    return i == 0 ? v.x : i == 1 ? v.y : i == 2 ? v.z : v.w;
}

// typed quad loaders (u8 spikes are exactly 0/1 -> conversion exact)
__device__ __forceinline__ float4 load_quad(const float* p) {
    return *(const float4*)p;
}
__device__ __forceinline__ float4 load_quad(const unsigned char* p) {
    uchar4 c = *(const uchar4*)p;
    return make_float4((float)c.x, (float)c.y, (float)c.z, (float)c.w);
}

// ---------------- weight packing: [co][ci][ky][WROW] 16B-aligned rows ---------
__global__ void pack_weights_kernel(const float* __restrict__ w1,
                                    const float* __restrict__ w2,
                                    const float* __restrict__ w3,
                                    float* __restrict__ wp)
{
    int i = blockIdx.x * blockDim.x + threadIdx.x;
    if (i < 1280) {                       // w1: [16][2][5][8], K=5
        int kx = i % 8; int r = i / 8;
        int ky = r % 5; r /= 5;
        int ci = r % 2; int co = r / 2;
        wp[W1_OFF + i] = (kx < 5) ? w1[((co * 2 + ci) * 5 + ky) * 5 + kx] : 0.0f;
    } else if (i < 1280 + 6144) {         // w2: [32][16][3][4], K=3
        int k = i - 1280;
        int kx = k % 4; int r = k / 4;
        int ky = r % 3; r /= 3;
        int ci = r % 16; int co = r / 16;
        wp[W2_OFF + k] = (kx < 3) ? w2[((co * 16 + ci) * 3 + ky) * 3 + kx] : 0.0f;
    } else if (i < 1280 + 6144 + 24576) { // w3: [64][32][3][4], K=3
        int k = i - 1280 - 6144;
        int kx = k % 4; int r = k / 4;
        int ky = r % 3; r /= 3;
        int ci = r % 32; int co = r / 32;
        wp[W3_OFF + k] = (kx < 3) ? w3[((co * 32 + ci) * 3 + ky) * 3 + kx] : 0.0f;
    }
}

// ---------------- input fp32 {0,1} -> u8 (exact) ----------------
__global__ void x_to_u8_kernel(const float* __restrict__ x, unsigned char* __restrict__ y)
{
    int i = blockIdx.x * blockDim.x + threadIdx.x;
    if (i < 1387200) {   // 8*2*34*34*300 / 4
        float4 v = ((const float4*)x)[i];
        ((uchar4*)y)[i] = make_uchar4((unsigned char)v.x, (unsigned char)v.y,
                                      (unsigned char)v.z, (unsigned char)v.w);
    }
}

// ---------------- conv (per-timestep 2D conv, T innermost, float4 over time) ---
// block: (b, yo, t-chunk of 4*TPQ steps). threads (TPQ, 32).
// tx owns one timestep quad; ty owns one (co-group, xo-group) item:
// COB=4 output channels x XR=4 x-positions. Weights come from the packed
// [co][ci][ky][WROW] layout -> one LDG.128 per (j,ky-row-chunk).
template <typename IT, int IN_TS,
          int Ci, int Hi, int Wi, int Co, int Ho, int Wo, int K, int PAD, int TPQ,
          int WROW>
__global__ void __launch_bounds__(TPQ * 32, 2)
conv_kernel(const IT* __restrict__ in, const float* __restrict__ w,
            float* __restrict__ out)
{
    constexpr int WT  = Wo + K - 1;
    constexpr int XR  = 4;
    constexpr int COB = 4;
    constexpr int XG  = Wo / XR;
    constexpr int CG  = Co / COB;
    static_assert(XG * CG == 32, "one item per ty");
    constexpr int TCH = 4 * TPQ;
    constexpr int NTC = (T_STEPS + TCH - 1) / TCH;
    constexpr int NTH = TPQ * 32;

    extern __shared__ char smraw[];
    float4* sm4 = (float4*)smraw;

    int bid = blockIdx.x;
    int tc  = bid % NTC;
    int yo  = (bid / NTC) % Ho;
    int b   = bid / (NTC * Ho);
    int t0  = tc * TCH;

    int tid = threadIdx.y * TPQ + threadIdx.x;

    // ---- load padded input tile as float4 quads: [Ci][K][WT][TPQ] ----
    constexpr int TILE4 = Ci * K * WT * TPQ;
    for (int flat = tid; flat < TILE4; flat += NTH) {
        int tt = flat % TPQ;
        int r  = flat / TPQ;
        int xw = r % WT; r /= WT;
        int ky = r % K;
        int ci = r / K;
        int xi = xw - PAD;
        int yi = yo - PAD + ky;
        int t  = t0 + 4 * tt;
        float4 v = make_float4(0.0f, 0.0f, 0.0f, 0.0f);
        if (xi >= 0 && xi < Wi && yi >= 0 && yi < Hi && t < T_STEPS)
            v = load_quad(&in[((((size_t)b * Ci + ci) * Hi + yi) * Wi + xi) * IN_TS + t]);
        sm4[flat] = v;
    }
    __syncthreads();

    int tx = threadIdx.x;
    int t  = t0 + 4 * tx;
    int item = threadIdx.y;
    int co0 = (item / XG) * COB;
    int xo0 = (item % XG) * XR;

    float4 acc[COB][XR];
#pragma unroll
    for (int j = 0; j < COB; j++)
#pragma unroll
        for (int r = 0; r < XR; r++) acc[j][r] = make_float4(0.0f, 0.0f, 0.0f, 0.0f);

    for (int ci = 0; ci < Ci; ci++) {
#pragma unroll
        for (int ky = 0; ky < K; ky++) {
            // input window (shared across all COB channels)
            float4 v[K + XR - 1];
            const float4* sp = &sm4[((ci * K + ky) * WT + xo0) * TPQ + tx];
#pragma unroll
            for (int j = 0; j < K + XR - 1; j++) v[j] = sp[j * TPQ];
            // packed weights: WROW/4 LDG.128 per output channel
            float4 wq[COB][WROW / 4];
#pragma unroll
            for (int j = 0; j < COB; j++)
#pragma unroll
                for (int p = 0; p < WROW / 4; p++)
                    wq[j][p] = *(const float4*)&w[(((size_t)(co0 + j) * Ci + ci) * K + ky) * WROW + 4 * p];
            // accumulate: per-output order stays (ci, ky, kx) ascending -> exact
#pragma unroll
            for (int kx = 0; kx < K; kx++)
#pragma unroll
                for (int j = 0; j < COB; j++)
#pragma unroll
                    for (int r = 0; r < XR; r++)
                        ffma4(acc[j][r], v[kx + r], f4_get(wq[j][kx >> 2], kx & 3));
        }
    }

    if (t < T_STEPS) {
#pragma unroll
        for (int j = 0; j < COB; j++)
#pragma unroll
            for (int r = 0; r < XR; r++)
                *(float4*)&out[((((size_t)b * Co + co0 + j) * Ho + yo) * Wo + xo0 + r) * T_STEPS + t]
                    = acc[j][r];
    }
}

// ---------------- fused spike -> 2x2 sum-pool (x11) -> spike, u8 out ----------
// WARP-COOPERATIVE: 4 lanes per pooled neuron; 16-step pipelined.
__device__ __forceinline__ unsigned int pool_quad(float4 uv, float (&bufp)[10],
                                                  float (&bp)[10]) {
    float p0 = spike_step(uv.x, bufp);
    float p1 = spike_step(uv.y, bufp);
    float p2 = spike_step(uv.z, bufp);
    float p3 = spike_step(uv.w, bufp);
    p0 += __shfl_xor_sync(0xffffffffu, p0, 1); p0 += __shfl_xor_sync(0xffffffffu, p0, 2);
    p1 += __shfl_xor_sync(0xffffffffu, p1, 1); p1 += __shfl_xor_sync(0xffffffffu, p1, 2);
    p2 += __shfl_xor_sync(0xffffffffu, p2, 1); p2 += __shfl_xor_sync(0xffffffffu, p2, 2);
    p3 += __shfl_xor_sync(0xffffffffu, p3, 1); p3 += __shfl_xor_sync(0xffffffffu, p3, 2);
    unsigned int e0 = (unsigned int)spike_step(11.0f * p0, bp);
    unsigned int e1 = (unsigned int)spike_step(11.0f * p1, bp);
    unsigned int e2 = (unsigned int)spike_step(11.0f * p2, bp);
    unsigned int e3 = (unsigned int)spike_step(11.0f * p3, bp);
    return e0 | (e1 << 8) | (e2 << 16) | (e3 << 24);
}

__global__ void __launch_bounds__(256)
spikepool_kernel(const float* __restrict__ u, unsigned char* __restrict__ s,
                 int C, int Ho, int Wo)
{
    int idx = blockIdx.x * blockDim.x + threadIdx.x;
    int sub = idx & 3;        // which parent (dy = sub>>1, dx = sub&1)
    int n   = idx >> 2;       // pooled neuron
    int total = 8 * C * Ho * Wo;
    if (n >= total) return;
    int x  = n % Wo;
    int y  = (n / Wo) % Ho;
    int cb = n / (Wo * Ho);   // b*C + c

    int dy = sub >> 1, dx = sub & 1;
    size_t base = (((size_t)cb * (2 * Ho) + 2 * y + dy) * (2 * Wo) + 2 * x + dx) * T_STEPS;
    const float4* up = (const float4*)(u + base);
    unsigned char* sp = s + (size_t)n * TS_U8;

    float bufp[10], bp[10];
#pragma unroll
    for (int j = 0; j < 10; j++) { bufp[j] = 0.0f; bp[j] = 0.0f; }

    for (int g = 0; g < 18; g++) {
        float4 v[4];
#pragma unroll
        for (int i = 0; i < 4; i++) v[i] = up[g * 4 + i];
        unsigned int wd[4];
#pragma unroll
        for (int i = 0; i < 4; i++) wd[i] = pool_quad(v[i], bufp, bp);
        if (sub == 0)
            ((uint4*)sp)[g] = make_uint4(wd[0], wd[1], wd[2], wd[3]);
    }
    {
        float4 v[3];
#pragma unroll
        for (int i = 0; i < 3; i++) v[i] = up[72 + i];
#pragma unroll
        for (int i = 0; i < 3; i++) {
            unsigned int wd = pool_quad(v[i], bufp, bp);
            if (sub == 0) ((unsigned int*)sp)[72 + i] = wd;
        }
    }
}

// ---------------- spike with u8 output (layer 5), 16-step pipelined ----------
__global__ void __launch_bounds__(256)
spike_u8_kernel(const float* __restrict__ u, unsigned char* __restrict__ s, int nNeurons)
{
    int n = blockIdx.x * blockDim.x + threadIdx.x;
    if (n >= nNeurons) return;
    const float4* up = (const float4*)(u + (size_t)n * T_STEPS);
    unsigned char* sp = s + (size_t)n * TS_U8;
    float buf[10];
#pragma unroll
    for (int j = 0; j < 10; j++) buf[j] = 0.0f;

    for (int g = 0; g < 18; g++) {
        float4 v[4];
#pragma unroll
        for (int i = 0; i < 4; i++) v[i] = up[g * 4 + i];
        unsigned int wd[4];
#pragma unroll
        for (int i = 0; i < 4; i++) {
            unsigned int e0 = (unsigned int)spike_step(v[i].x, buf);
            unsigned int e1 = (unsigned int)spike_step(v[i].y, buf);
            unsigned int e2 = (unsigned int)spike_step(v[i].z, buf);
            unsigned int e3 = (unsigned int)spike_step(v[i].w, buf);
            wd[i] = e0 | (e1 << 8) | (e2 << 16) | (e3 << 24);
        }
        ((uint4*)sp)[g] = make_uint4(wd[0], wd[1], wd[2], wd[3]);
    }
    {
        float4 v[3];
#pragma unroll
        for (int i = 0; i < 3; i++) v[i] = up[72 + i];
#pragma unroll
        for (int i = 0; i < 3; i++) {
            unsigned int e0 = (unsigned int)spike_step(v[i].x, buf);
            unsigned int e1 = (unsigned int)spike_step(v[i].y, buf);
            unsigned int e2 = (unsigned int)spike_step(v[i].z, buf);
            unsigned int e3 = (unsigned int)spike_step(v[i].w, buf);
            ((unsigned int*)sp)[72 + i] = e0 | (e1 << 8) | (e2 << 16) | (e3 << 24);
        }
    }
}

// ---------------- FC: block = (b, t-quad); s5 chunk staged in smem --------------
__global__ void __launch_bounds__(320, 3)
fc_kernel(const unsigned char* __restrict__ s5, const float* __restrict__ wfc,
          float* __restrict__ u_out)
{
    constexpr int NQ = T_STEPS / 4;   // 75
    int q = blockIdx.x % NQ;
    int b = blockIdx.x / NQ;
    int t0 = q * 4;

    extern __shared__ float4 s_sm[];  // [4096]
    int tid = threadIdx.y * 32 + threadIdx.x;

    const unsigned char* sb = s5 + (size_t)b * 4096 * TS_U8 + t0;
    for (int c = tid; c < 4096; c += 320) {
        uchar4 cc = *(const uchar4*)&sb[(size_t)c * TS_U8];
        s_sm[c] = make_float4((float)cc.x, (float)cc.y, (float)cc.z, (float)cc.w);
    }
    __syncthreads();

    int o    = threadIdx.y;   // 0..9
    int lane = threadIdx.x;   // 0..31
    const float* wo = wfc + o * 4096;

    float4 acc = make_float4(0.0f, 0.0f, 0.0f, 0.0f);
    for (int c = lane; c < 4096; c += 32) {
        float4 v = s_sm[c];
        float wgt = __ldg(&wo[c]);
        acc.x = fmaf(v.x, wgt, acc.x);
        acc.y = fmaf(v.y, wgt, acc.y);
        acc.z = fmaf(v.z, wgt, acc.z);
        acc.w = fmaf(v.w, wgt, acc.w);
    }
#pragma unroll
    for (int d = 16; d >= 1; d >>= 1) {
        acc.x += __shfl_xor_sync(0xffffffffu, acc.x, d);
        acc.y += __shfl_xor_sync(0xffffffffu, acc.y, d);
        acc.z += __shfl_xor_sync(0xffffffffu, acc.z, d);
        acc.w += __shfl_xor_sync(0xffffffffu, acc.w, d);
    }
    if (lane == 0)
        *(float4*)&u_out[(size_t)(b * 10 + o) * T_STEPS + t0] = acc;
}

// ---------------- final spike on 80 neurons ----------------
__global__ void spike_final_kernel(const float* __restrict__ u, float* __restrict__ out)
{
    int n = threadIdx.x;
    if (n >= 80) return;
    const float4* up = (const float4*)(u + (size_t)n * T_STEPS);
    float4*       sp = (float4*)(out + (size_t)n * T_STEPS);
    float buf[10];
#pragma unroll
    for (int j = 0; j < 10; j++) buf[j] = 0.0f;
    for (int q = 0; q < T_STEPS / 4; q++) {
        float4 uv = up[q];
        float4 ev;
        ev.x = spike_step(uv.x, buf);
        ev.y = spike_step(uv.y, buf);
        ev.z = spike_step(uv.z, buf);
        ev.w = spike_step(uv.w, buf);
        sp[q] = ev;
    }
}

// ---------------- launcher ----------------
extern "C" void kernel_launch(void* const* d_in, const int* in_sizes, int n_in,
                              void* d_out, int out_size)
{
    const float* x   = (const float*)d_in[0];   // [8,2,34,34,300]
    const float* w1  = (const float*)d_in[1];   // [16,2,5,5]
    const float* w2  = (const float*)d_in[2];   // [32,16,3,3]
    const float* w3  = (const float*)d_in[3];   // [64,32,3,3]
    const float* wfc = (const float*)d_in[4];   // [10,64,8,8]
    float* out = (float*)d_out;                 // [8,10,1,1,300]

    float *A = nullptr, *W = nullptr;
    unsigned char *S = nullptr;
    cudaGetSymbolAddress((void**)&A, g_bufA);
    cudaGetSymbolAddress((void**)&S, g_bufS);
    cudaGetSymbolAddress((void**)&W, g_bufW);

    // smem bytes: Ci*K*WT*TPQ * sizeof(float4)
    constexpr int SM1 = 2  * 5 * 36 * 8 * 16;   //  46080  (TPQ=8, 32-step chunks)
    constexpr int SM2 = 16 * 3 * 18 * 8 * 16;   // 110592  (TPQ=8)
    constexpr int SM3 = 32 * 3 * 10 * 6 * 16;   //  92160  (TPQ=6, 24-step chunks)
    constexpr int SMF = 4096 * 16;              //  65536  (FC chunk)

    cudaFuncSetAttribute((const void*)conv_kernel<unsigned char,T_STEPS,2,34,34,16,32,32,5,1,8,8>,
                         cudaFuncAttributeMaxDynamicSharedMemorySize, SM1);
    cudaFuncSetAttribute((const void*)conv_kernel<unsigned char,TS_U8,16,16,16,32,16,16,3,1,8,4>,
                         cudaFuncAttributeMaxDynamicSharedMemorySize, SM2);
    cudaFuncSetAttribute((const void*)conv_kernel<unsigned char,TS_U8,32,8,8,64,8,8,3,1,6,4>,
                         cudaFuncAttributeMaxDynamicSharedMemorySize, SM3);
    cudaFuncSetAttribute((const void*)fc_kernel,
                         cudaFuncAttributeMaxDynamicSharedMemorySize, SMF);

    constexpr int NTC8 = 10;   // ceil(300/32)
    constexpr int NTC6 = 13;   // ceil(300/24)

    // prep: pack weights, convert input to u8 (into S, free at this point)
    pack_weights_kernel<<<(32000 + 255) / 256, 256>>>(w1, w2, w3, W);
    x_to_u8_kernel<<<(1387200 + 255) / 256, 256>>>(x, S);

    // L1: conv 2->16 5x5 pad1 : S(x_u8) -> A (u1)  [8,16,32,32,300]
    conv_kernel<unsigned char,T_STEPS,2,34,34,16,32,32,5,1,8,8>
        <<<8 * 32 * NTC8, dim3(8, 32), SM1>>>(S, W + W1_OFF, A);
    // spike1 + pool + spike2 fused (4 lanes/neuron): A -> S (s2, u8)
    spikepool_kernel<<<(32768 * 4) / 256, 256>>>(A, S, 16, 16, 16);
    // L2: conv 16->32 3x3 pad1 : S -> A (u3) [8,32,16,16,300]
    conv_kernel<unsigned char,TS_U8,16,16,16,32,16,16,3,1,8,4>
        <<<8 * 16 * NTC8, dim3(8, 32), SM2>>>(S, W + W2_OFF, A);
    // spike3 + pool + spike4 fused (4 lanes/neuron): A -> S (s4, u8)
    spikepool_kernel<<<(16384 * 4) / 256, 256>>>(A, S, 32, 8, 8);
    // L3: conv 32->64 3x3 pad1 : S -> A (u5) [8,64,8,8,300]
    conv_kernel<unsigned char,TS_U8,32,8,8,64,8,8,3,1,6,4>
        <<<8 * 8 * NTC6, dim3(6, 32), SM3>>>(S, W + W3_OFF, A);
    // spike5: A -> S (s5, u8)
    spike_u8_kernel<<<32768 / 256, 256>>>(A, S, 32768);
    // FC: S (s5) -> A (u6) [8,10,300]
    fc_kernel<<<8 * 75, dim3(32, 10), SMF>>>(S, wfc, A);
    // final spike: A -> out
    spike_final_kernel<<<1, 96>>>(A, out);
}